// round 9
// baseline (speedup 1.0000x reference)
#include <cuda_runtime.h>
#include <cstdint>
#include <cstddef>

// ---------------- problem dims ----------------
// B=32, T=10, NOV=3, N=128, F=16, NF=5, EF=2, C=4, SL=2, HID=2048
#define LEAKY(x) ((x) > 0.0f ? (x) : 0.01f * (x))

constexpr int Bc = 32;
constexpr int Nc = 128;
constexpr int HIDc = 2048;
constexpr int ROWc = 389;      // 3N+NF
constexpr int FLATc = 8192;    // C*N*F
constexpr int KSPLIT = 32;     // k4 K-split factor

// ---------------- scratch (__device__ globals; no allocs) ----------------
__device__ float g_a1[Bc * Nc * Nc];
__device__ float g_a2[Bc * Nc * Nc];
__device__ float g_rs1[Bc * Nc];
__device__ float g_rs2[Bc * Nc];
__device__ float g_eep[2 * Bc * Nc * 16];   // edge-enc halves
__device__ float g_x2[(size_t)Bc * 10 * 4 * Nc * 16];
__device__ float g_flat[Bc * FLATc];
__device__ float g_part2[(size_t)2 * KSPLIT * Bc * HIDc];
__device__ float g_hh[2 * Bc * HIDc];

// ---------------- helpers ----------------
__device__ __forceinline__ unsigned long long f2pk(float x, float y) {
    unsigned long long d;
    asm("mov.b64 %0, {%1, %2};" : "=l"(d) : "f"(x), "f"(y));
    return d;
}
__device__ __forceinline__ void f2un(float& x, float& y, unsigned long long v) {
    asm("mov.b64 {%0, %1}, %2;" : "=f"(x), "=f"(y) : "l"(v));
}
__device__ __forceinline__ unsigned long long fma2(unsigned long long a,
                                                   unsigned long long b,
                                                   unsigned long long c) {
    unsigned long long d;
    asm("fma.rn.f32x2 %0, %1, %2, %3;" : "=l"(d) : "l"(a), "l"(b), "l"(c));
    return d;
}
__device__ __forceinline__ void cp16(uint32_t smem_dst, const void* gsrc) {
    asm volatile("cp.async.cg.shared.global [%0], [%1], 16;\n" ::
                 "r"(smem_dst), "l"(gsrc));
}
__device__ __forceinline__ void cp4(uint32_t smem_dst, const void* gsrc) {
    asm volatile("cp.async.ca.shared.global [%0], [%1], 4;\n" ::
                 "r"(smem_dst), "l"(gsrc));
}
__device__ __forceinline__ void cp_commit() {
    asm volatile("cp.async.commit_group;\n");
}
__device__ __forceinline__ void cp_wait0() {
    asm volatile("cp.async.wait_group 0;\n" ::: "memory");
}

// ============================================================
// K1: grid (32, 3), block 512, dyn smem 128*129*4
//  y==0: adjacency normalization chain (a1, rs1, a2, rs2)
//  y==1/2: edge-encoder i-half -> g_eep[half]
// ============================================================
__global__ void __launch_bounds__(512)
k1_prep(const float* __restrict__ inp,
        const float* __restrict__ We,
        const float* __restrict__ be) {
    extern __shared__ float s_a[];       // [128][129] (y>0 uses 64 rows)
    __shared__ float s_d[128];
    __shared__ float s_we[32];
    __shared__ float s_be[16];
    __shared__ float s_part[3 * 2048];
    const int b = blockIdx.x, role = blockIdx.y, tid = threadIdx.x;
    const size_t base = (size_t)b * 30 * 128 * ROWc;

    if (role != 0) {
        // ---- edge encoder for i in [h*64, h*64+64) ----
        const int h = role - 1;
        if (tid < 32) s_we[tid] = We[tid];
        if (tid >= 32 && tid < 48) s_be[tid - 32] = be[tid - 32];
        for (int idx = tid; idx < 64 * 128; idx += 512) {
            int i = idx >> 7, j = idx & 127;
            s_a[i * 129 + j] = inp[base + (size_t)(h * 64 + i) * ROWc + j];
        }
        __syncthreads();
        const int j = tid & 127;
        const int q = tid >> 7;
        float acc[16];
#pragma unroll
        for (int f = 0; f < 16; f++) acc[f] = 0.0f;
#pragma unroll 4
        for (int il = q * 16; il < q * 16 + 16; il++) {
            float a = s_a[il * 129 + j];
            const float* ep =
                inp + base + (size_t)(h * 64 + il) * ROWc + 128 + 2 * j;
            float e0 = ep[0], e1 = ep[1];
#pragma unroll
            for (int f = 0; f < 16; f++) {
                float v = fmaf(e0, s_we[f], fmaf(e1, s_we[16 + f], s_be[f]));
                v = LEAKY(v);
                acc[f] = fmaf(v, a, acc[f]);
            }
        }
        if (q) {
#pragma unroll
            for (int f = 0; f < 16; f++)
                s_part[(q - 1) * 2048 + j * 16 + f] = acc[f];
        }
        __syncthreads();
        if (q == 0) {
#pragma unroll
            for (int f = 0; f < 16; f++)
                g_eep[h * 65536 + (b * 128 + j) * 16 + f] =
                    acc[f] + s_part[j * 16 + f] + s_part[2048 + j * 16 + f] +
                    s_part[4096 + j * 16 + f];
        }
        return;
    }

    // ---- role 0: adjacency chain ----
    for (int idx = tid; idx < 128 * 128; idx += 512) {
        int i = idx >> 7, j = idx & 127;
        s_a[i * 129 + j] = inp[base + (size_t)i * ROWc + j];
    }
    __syncthreads();
    {
        const int i = tid & 127, q = tid >> 7;
        float p = 0.0f;
        for (int j = q * 32; j < q * 32 + 32; j++)
            p += (j == i) ? 1.0f : s_a[i * 129 + j];
        s_part[q * 128 + i] = p;
        __syncthreads();
        if (tid < 128) {
            float s = s_part[tid] + s_part[128 + tid] + s_part[256 + tid] +
                      s_part[384 + tid];
            s_d[tid] = 1.0f / sqrtf(fmaxf(s, 1.0f));
        }
        __syncthreads();
    }
    for (int idx = tid; idx < 128 * 128; idx += 512) {
        int i = idx >> 7, j = idx & 127;
        float a0 = (i == j) ? 1.0f : s_a[i * 129 + j];
        float v = s_d[i] * a0 * s_d[j];
        s_a[i * 129 + j] = v;
        g_a1[b * 16384 + idx] = v;
    }
    __syncthreads();
    {
        const int i = tid & 127, q = tid >> 7;
        float p = 0.0f;
        for (int j = q * 32; j < q * 32 + 32; j++) p += s_a[i * 129 + j];
        s_part[q * 128 + i] = p;
        __syncthreads();
        if (tid < 128) {
            float s = s_part[tid] + s_part[128 + tid] + s_part[256 + tid] +
                      s_part[384 + tid];
            g_rs1[b * 128 + tid] = s;
            s_d[tid] = 1.0f / sqrtf(fmaxf(s, 1.0f));
        }
        __syncthreads();
    }
    for (int idx = tid; idx < 128 * 128; idx += 512) {
        int i = idx >> 7, j = idx & 127;
        float v = s_d[i] * s_a[i * 129 + j] * s_d[j];
        s_a[i * 129 + j] = v;
        g_a2[b * 16384 + idx] = v;
    }
    __syncthreads();
    {
        const int i = tid & 127, q = tid >> 7;
        float p = 0.0f;
        for (int j = q * 32; j < q * 32 + 32; j++) p += s_a[i * 129 + j];
        s_part[q * 128 + i] = p;
        __syncthreads();
        if (tid < 128)
            g_rs2[b * 128 + tid] = s_part[tid] + s_part[128 + tid] +
                                   s_part[256 + tid] + s_part[384 + tid];
    }
}

// ============================================================
// K2: per-(b,t) GCN, 512 threads, f32x2 packed math,
// a1/a2 loads overlapped via cp.async.
// grid (32,10), block 512, dynamic smem = 128*129*4
// ============================================================
__global__ void __launch_bounds__(512)
k2_gcn(const float* __restrict__ inp,
       const float* __restrict__ Wn,
       const float* __restrict__ bn,
       const float* __restrict__ Wg,
       const float* __restrict__ bgl,
       const float* __restrict__ gb) {
    extern __shared__ float s_a[];       // [128][129]
    __shared__ float s_xs[2048];
    __shared__ float s_z[2048];
    __shared__ float s_wgT[2048];        // [l][c][o][f]
    __shared__ float s_bgl[128];
    __shared__ float s_gb[64];
    __shared__ float s_wn[80];
    __shared__ float s_bn[16];
    __shared__ float s_rs[256];

    const int b = blockIdx.x, t = blockIdx.y, tid = threadIdx.x;
    const uint32_t sa_base = (uint32_t)__cvta_generic_to_shared(s_a);

    for (int idx = tid; idx < 16384; idx += 512) {
        int i = idx >> 7, j = idx & 127;
        cp4(sa_base + (uint32_t)(i * 129 + j) * 4, &g_a1[b * 16384 + idx]);
    }
    cp_commit();

    for (int i = tid; i < 2048; i += 512) {
        int o = i & 15, f = (i >> 4) & 15, lc = i >> 8;
        s_wgT[(lc * 16 + o) * 16 + f] = Wg[i];
    }
    if (tid < 128) s_bgl[tid] = bgl[tid];
    if (tid < 64) s_gb[tid] = gb[tid];
    if (tid < 80) s_wn[tid] = Wn[tid];
    if (tid < 16) s_bn[tid] = bn[tid];
    if (tid < 128) s_rs[tid] = g_rs1[b * 128 + tid];
    if (tid >= 128 && tid < 256) s_rs[tid] = g_rs2[b * 128 + tid - 128];
    __syncthreads();

    const int n = tid & 127;
    const int f0 = (tid >> 7) * 4;

    // xs = edge_enc(sum of halves) + sum_v leaky(node@Wn + bn)
    {
        float acc[4];
        const float* e0 = &g_eep[(b * 128 + n) * 16 + f0];
        const float* e1 = &g_eep[65536 + (b * 128 + n) * 16 + f0];
#pragma unroll
        for (int f = 0; f < 4; f++) acc[f] = e0[f] + e1[f];
#pragma unroll
        for (int v = 0; v < 3; v++) {
            const float* np =
                inp + ((size_t)(b * 30 + t * 3 + v) * 128 + n) * ROWc + 384;
            float nk0 = np[0], nk1 = np[1], nk2 = np[2], nk3 = np[3], nk4 = np[4];
#pragma unroll
            for (int f = 0; f < 4; f++) {
                int fc = f0 + f;
                float s = s_bn[fc];
                s = fmaf(nk0, s_wn[fc], s);
                s = fmaf(nk1, s_wn[16 + fc], s);
                s = fmaf(nk2, s_wn[32 + fc], s);
                s = fmaf(nk3, s_wn[48 + fc], s);
                s = fmaf(nk4, s_wn[64 + fc], s);
                acc[f] += LEAKY(s);
            }
        }
        *(float4*)&s_xs[n * 16 + f0] = make_float4(acc[0], acc[1], acc[2], acc[3]);
    }
    cp_wait0();
    __syncthreads();

    // z1 = a1 @ xs
    {
        unsigned long long za0 = 0ULL, za1 = 0ULL;
#pragma unroll 8
        for (int m = 0; m < 128; m++) {
            float a = s_a[n * 129 + m];
            unsigned long long ap = f2pk(a, a);
            ulonglong2 x = *(const ulonglong2*)&s_xs[m * 16 + f0];
            za0 = fma2(ap, x.x, za0);
            za1 = fma2(ap, x.y, za1);
        }
        ulonglong2 zo; zo.x = za0; zo.y = za1;
        *(ulonglong2*)&s_z[n * 16 + f0] = zo;
    }
    __syncthreads();

    // a2 copy overlaps layer-1 mix
    for (int idx = tid; idx < 16384; idx += 512) {
        int i = idx >> 7, j = idx & 127;
        cp4(sa_base + (uint32_t)(i * 129 + j) * 4, &g_a2[b * 16384 + idx]);
    }
    cp_commit();

    // layer-1 channel mix
    {
        unsigned long long zp[8];
        ulonglong2 q0 = *(const ulonglong2*)&s_z[n * 16];
        ulonglong2 q1 = *(const ulonglong2*)&s_z[n * 16 + 4];
        ulonglong2 q2 = *(const ulonglong2*)&s_z[n * 16 + 8];
        ulonglong2 q3 = *(const ulonglong2*)&s_z[n * 16 + 12];
        zp[0] = q0.x; zp[1] = q0.y; zp[2] = q1.x; zp[3] = q1.y;
        zp[4] = q2.x; zp[5] = q2.y; zp[6] = q3.x; zp[7] = q3.y;
        float rs4 = 4.0f * s_rs[n];
        float outv[4];
#pragma unroll
        for (int o = 0; o < 4; o++) {
            int oc = f0 + o;
            float sum = 0.0f;
#pragma unroll
            for (int c = 0; c < 4; c++) {
                const unsigned long long* wp =
                    (const unsigned long long*)&s_wgT[(c * 16 + oc) * 16];
                unsigned long long a2v = 0ULL;
#pragma unroll
                for (int i = 0; i < 8; i++) a2v = fma2(zp[i], wp[i], a2v);
                float ux, uy; f2un(ux, uy, a2v);
                float u = ux + uy + fmaf(rs4, s_bgl[c * 16 + oc], s_gb[c * 16 + oc]);
                sum += LEAKY(u);
            }
            outv[o] = sum;
        }
        *(float4*)&s_xs[n * 16 + f0] =
            make_float4(outv[0], outv[1], outv[2], outv[3]);
    }
    cp_wait0();
    __syncthreads();

    // z2 = a2 @ xs2
    {
        unsigned long long za0 = 0ULL, za1 = 0ULL;
#pragma unroll 8
        for (int m = 0; m < 128; m++) {
            float a = s_a[n * 129 + m];
            unsigned long long ap = f2pk(a, a);
            ulonglong2 x = *(const ulonglong2*)&s_xs[m * 16 + f0];
            za0 = fma2(ap, x.x, za0);
            za1 = fma2(ap, x.y, za1);
        }
        ulonglong2 zo; zo.x = za0; zo.y = za1;
        *(ulonglong2*)&s_z[n * 16 + f0] = zo;
    }
    __syncthreads();

    // layer-2 channel mix -> g_x2 (float4 stores)
    {
        unsigned long long zp[8];
        ulonglong2 q0 = *(const ulonglong2*)&s_z[n * 16];
        ulonglong2 q1 = *(const ulonglong2*)&s_z[n * 16 + 4];
        ulonglong2 q2 = *(const ulonglong2*)&s_z[n * 16 + 8];
        ulonglong2 q3 = *(const ulonglong2*)&s_z[n * 16 + 12];
        zp[0] = q0.x; zp[1] = q0.y; zp[2] = q1.x; zp[3] = q1.y;
        zp[4] = q2.x; zp[5] = q2.y; zp[6] = q3.x; zp[7] = q3.y;
        float rs4 = 4.0f * s_rs[128 + n];
        size_t obase = ((size_t)(b * 10 + t) * 4) * 2048 + n * 16 + f0;
#pragma unroll
        for (int c = 0; c < 4; c++) {
            float ov[4];
#pragma unroll
            for (int o = 0; o < 4; o++) {
                int oc = f0 + o;
                const unsigned long long* wp =
                    (const unsigned long long*)&s_wgT[((4 + c) * 16 + oc) * 16];
                unsigned long long a2v = 0ULL;
#pragma unroll
                for (int i = 0; i < 8; i++) a2v = fma2(zp[i], wp[i], a2v);
                float ux, uy; f2un(ux, uy, a2v);
                float u = ux + uy +
                          fmaf(rs4, s_bgl[64 + c * 16 + oc], s_gb[c * 16 + oc]);
                ov[o] = LEAKY(u);
            }
            *(float4*)&g_x2[obase + c * 2048] =
                make_float4(ov[0], ov[1], ov[2], ov[3]);
        }
    }
}

// ============================================================
// K3: reduce over t -> flat (float4). grid 256, block 256
// ============================================================
__global__ void k3_reduce() {
    int idx4 = blockIdx.x * 256 + threadIdx.x;   // 0..65535
    int b = idx4 >> 11;
    int j4 = idx4 & 2047;
    const float4* p = (const float4*)&g_x2[(size_t)b * 10 * 8192] + j4;
    float4 s = make_float4(0.f, 0.f, 0.f, 0.f);
#pragma unroll
    for (int t = 0; t < 10; t++) {
        float4 v = p[t * 2048];
        s.x += v.x; s.y += v.y; s.z += v.z; s.w += v.w;
    }
    ((float4*)g_flat)[idx4] = s;
}

// ============================================================
// K4 v7: flat(32x8192) @ W(8192x2048) x2 heads.
// Lane owns 8 cols (4 f32x2 acc / row), 8 rows per warp.
// d via broadcast LDS.128 (conflict-free), W double-buffered cp.async.
// grid (8, 32, 2) = 512 CTAs, block 128, 4 CTAs/SM.
// ============================================================
__global__ void __launch_bounds__(128, 4)
k4_gemm(const float* __restrict__ Wc1, const float* __restrict__ Wa1) {
    __shared__ float s_w[2][16][256];     // 32 KB
    __shared__ float4 s_fd[2][32][9];     // 9.2 KB, [row][kp] dup pairs
    const int tid = threadIdx.x;
    const int head = blockIdx.z;
    const float* __restrict__ W = head ? Wa1 : Wc1;
    const int colbase = blockIdx.x * 256;
    const int warp = tid >> 5, lane = tid & 31;
    const int rowbase = warp * 8;
    const int wcol = lane * 8;
    const int kbase = blockIdx.y * 256;

    const int frow = tid >> 2;        // 0..31
    const int fq = (tid & 3) * 4;     // k offset 0,4,8,12
    const int fkp = fq >> 1;          // kp slot 0,2,4,6

    const uint32_t sw0 = (uint32_t)__cvta_generic_to_shared(&s_w[0][0][0]);
    const uint32_t sw1 = (uint32_t)__cvta_generic_to_shared(&s_w[1][0][0]);

    unsigned long long acc[8][4];
#pragma unroll
    for (int r = 0; r < 8; r++) {
        acc[r][0] = 0ULL; acc[r][1] = 0ULL; acc[r][2] = 0ULL; acc[r][3] = 0ULL;
    }

    // prologue: stage-0 fills
    {
#pragma unroll
        for (int i = 0; i < 8; i++) {
            int idx = tid + i * 128;               // 0..1023 float4s
            int kk = idx >> 6, cc = idx & 63;
            cp16(sw0 + (uint32_t)(kk * 256 + cc * 4) * 4,
                 &W[(size_t)(kbase + kk) * 2048 + colbase + cc * 4]);
        }
        cp_commit();
        float4 fv = *(const float4*)&g_flat[frow * 8192 + kbase + fq];
        s_fd[0][frow][fkp] = make_float4(fv.x, fv.x, fv.y, fv.y);
        s_fd[0][frow][fkp + 1] = make_float4(fv.z, fv.z, fv.w, fv.w);
    }
    float4 fvn = *(const float4*)&g_flat[frow * 8192 + kbase + 16 + fq];

    for (int s = 0; s < 16; s++) {
        const int b = s & 1;
        cp_wait0();
        __syncthreads();
        if (s < 15) {
            const uint32_t swn = b ? sw0 : sw1;
            const int nb = b ^ 1;
            const int kn = kbase + (s + 1) * 16;
#pragma unroll
            for (int i = 0; i < 8; i++) {
                int idx = tid + i * 128;
                int kk = idx >> 6, cc = idx & 63;
                cp16(swn + (uint32_t)(kk * 256 + cc * 4) * 4,
                     &W[(size_t)(kn + kk) * 2048 + colbase + cc * 4]);
            }
            cp_commit();
            s_fd[nb][frow][fkp] = make_float4(fvn.x, fvn.x, fvn.y, fvn.y);
            s_fd[nb][frow][fkp + 1] = make_float4(fvn.z, fvn.z, fvn.w, fvn.w);
            if (s < 14)
                fvn = *(const float4*)&g_flat[frow * 8192 + kbase +
                                              (s + 2) * 16 + fq];
        }
#pragma unroll
        for (int kp = 0; kp < 8; kp++) {
            const int k = kp * 2;
            ulonglong2 w0a = *(const ulonglong2*)&s_w[b][k][wcol];
            ulonglong2 w0b = *(const ulonglong2*)&s_w[b][k][wcol + 4];
            ulonglong2 w1a = *(const ulonglong2*)&s_w[b][k + 1][wcol];
            ulonglong2 w1b = *(const ulonglong2*)&s_w[b][k + 1][wcol + 4];
#pragma unroll
            for (int r = 0; r < 8; r++) {
                ulonglong2 d = *(const ulonglong2*)&s_fd[b][rowbase + r][kp];
                acc[r][0] = fma2(d.x, w0a.x, acc[r][0]);
                acc[r][1] = fma2(d.x, w0a.y, acc[r][1]);
                acc[r][2] = fma2(d.x, w0b.x, acc[r][2]);
                acc[r][3] = fma2(d.x, w0b.y, acc[r][3]);
                acc[r][0] = fma2(d.y, w1a.x, acc[r][0]);
                acc[r][1] = fma2(d.y, w1a.y, acc[r][1]);
                acc[r][2] = fma2(d.y, w1b.x, acc[r][2]);
                acc[r][3] = fma2(d.y, w1b.y, acc[r][3]);
            }
        }
    }

    const size_t base = ((size_t)(head * KSPLIT + blockIdx.y)) * 65536;
    const int gcol = colbase + wcol;
#pragma unroll
    for (int r = 0; r < 8; r++) {
        float4 o0, o1;
        f2un(o0.x, o0.y, acc[r][0]);
        f2un(o0.z, o0.w, acc[r][1]);
        f2un(o1.x, o1.y, acc[r][2]);
        f2un(o1.z, o1.w, acc[r][3]);
        float* p = &g_part2[base + (size_t)(rowbase + r) * 2048 + gcol];
        *(float4*)p = o0;
        *(float4*)(p + 4) = o1;
    }
}

// ============================================================
// K5a: reduce K-split partials + bias + leaky (float4)
// grid (64, 2), block 256
// ============================================================
__global__ void k5a_act(const float* __restrict__ bc1,
                        const float* __restrict__ ba1) {
    const int head = blockIdx.y;
    const int i4 = blockIdx.x * 256 + threadIdx.x;   // 0..16383
    const int col4 = i4 & 511;
    float4 s = ((const float4*)(head ? ba1 : bc1))[col4];
    const float4* p = (const float4*)&g_part2[(size_t)head * KSPLIT * 65536];
#pragma unroll
    for (int pi = 0; pi < KSPLIT; pi++) {
        float4 v = p[(size_t)pi * 16384 + i4];
        s.x += v.x; s.y += v.y; s.z += v.z; s.w += v.w;
    }
    s.x = LEAKY(s.x); s.y = LEAKY(s.y); s.z = LEAKY(s.z); s.w = LEAKY(s.w);
    ((float4*)g_hh)[head * 16384 + i4] = s;
}

// ============================================================
// K5b: small heads, per-head CTAs + W2 prefetch.
// grid (32, 2), block 256
// ============================================================
__global__ void k5b_heads(const float* __restrict__ Wc2,
                          const float* __restrict__ bc2,
                          const float* __restrict__ Wc3,
                          const float* __restrict__ bc3,
                          const float* __restrict__ Wa2,
                          const float* __restrict__ ba2,
                          float* __restrict__ out) {
    __shared__ float s_h[2048];
    __shared__ float s_w[256 * 17];
    __shared__ float s_r[16];
    const int b = blockIdx.x, head = blockIdx.y, tid = threadIdx.x;
    const float* __restrict__ W2 = head ? Wa2 : Wc2;
    const float* __restrict__ b2 = head ? ba2 : bc2;

    {
        const float4* hs = (const float4*)&g_hh[head * 65536 + b * 2048];
        ((float4*)s_h)[tid] = hs[tid];
        ((float4*)s_h)[tid + 256] = hs[tid + 256];
    }
    const int w = tid >> 5, lane = tid & 31;
    float ps[2] = {0.0f, 0.0f};

    float rv[16];
#pragma unroll
    for (int i = 0; i < 16; i++) rv[i] = W2[tid + i * 256];

    for (int c = 0; c < 8; c++) {
        __syncthreads();
#pragma unroll
        for (int i = 0; i < 16; i++) {
            int idx = tid + i * 256;
            s_w[(idx >> 4) * 17 + (idx & 15)] = rv[i];
        }
        __syncthreads();
        if (c < 7) {
#pragma unroll
            for (int i = 0; i < 16; i++)
                rv[i] = W2[(c + 1) * 4096 + tid + i * 256];
        }
#pragma unroll
        for (int dd = 0; dd < 2; dd++) {
            const int f = w + dd * 8;
            float s = 0.0f;
#pragma unroll
            for (int ki = 0; ki < 8; ki++) {
                int k = ki * 32 + lane;
                s = fmaf(s_h[c * 256 + k], s_w[k * 17 + f], s);
            }
            ps[dd] += s;
        }
    }
#pragma unroll
    for (int dd = 0; dd < 2; dd++) {
        float s = ps[dd];
#pragma unroll
        for (int off = 16; off; off >>= 1) s += __shfl_down_sync(0xffffffffu, s, off);
        if (lane == 0) {
            int f = w + dd * 8;
            float v = s + b2[f];
            s_r[f] = LEAKY(v);
        }
    }
    __syncthreads();
    if (head == 0) {
        if (tid == 0) {
            float cr = bc3[0];
#pragma unroll
            for (int f = 0; f < 16; f++) cr = fmaf(s_r[f], Wc3[f], cr);
            out[b] = cr;
        }
    } else {
        if (tid < 16) out[32 + b * 16 + tid] = s_r[tid];
    }
}

// ============================================================
extern "C" void kernel_launch(void* const* d_in, const int* in_sizes, int n_in,
                              void* d_out, int out_size) {
    (void)in_sizes; (void)n_in; (void)out_size;
    const float* inp = (const float*)d_in[0];
    const float* We  = (const float*)d_in[1];
    const float* be  = (const float*)d_in[2];
    const float* Wn  = (const float*)d_in[3];
    const float* bn  = (const float*)d_in[4];
    const float* Wg  = (const float*)d_in[5];
    const float* bgl = (const float*)d_in[6];
    const float* gb  = (const float*)d_in[7];
    const float* Wc1 = (const float*)d_in[8];
    const float* bc1 = (const float*)d_in[9];
    const float* Wc2 = (const float*)d_in[10];
    const float* bc2 = (const float*)d_in[11];
    const float* Wc3 = (const float*)d_in[12];
    const float* bc3 = (const float*)d_in[13];
    const float* Wa1 = (const float*)d_in[14];
    const float* ba1 = (const float*)d_in[15];
    const float* Wa2 = (const float*)d_in[16];
    const float* ba2 = (const float*)d_in[17];

    const int dyn = 128 * 129 * 4;  // 66048 B
    cudaFuncSetAttribute(k1_prep, cudaFuncAttributeMaxDynamicSharedMemorySize, dyn);
    cudaFuncSetAttribute(k2_gcn, cudaFuncAttributeMaxDynamicSharedMemorySize, dyn);

    k1_prep<<<dim3(32, 3), 512, dyn>>>(inp, We, be);
    k2_gcn<<<dim3(32, 10), 512, dyn>>>(inp, Wn, bn, Wg, bgl, gb);
    k3_reduce<<<256, 256>>>();
    k4_gemm<<<dim3(8, KSPLIT, 2), 128>>>(Wc1, Wa1);
    k5a_act<<<dim3(64, 2), 256>>>(bc1, ba1);
    k5b_heads<<<dim3(32, 2), 256>>>(Wc2, bc2, Wc3, bc3, Wa2, ba2, (float*)d_out);
}

// round 10
// speedup vs baseline: 1.0425x; 1.0425x over previous
#include <cuda_runtime.h>
#include <cstdint>
#include <cstddef>

// ---------------- problem dims ----------------
// B=32, T=10, NOV=3, N=128, F=16, NF=5, EF=2, C=4, SL=2, HID=2048
#define LEAKY(x) ((x) > 0.0f ? (x) : 0.01f * (x))

constexpr int Bc = 32;
constexpr int Nc = 128;
constexpr int HIDc = 2048;
constexpr int ROWc = 389;      // 3N+NF
constexpr int FLATc = 8192;    // C*N*F
constexpr int KSPLIT = 16;     // k4 K-split factor (512 k per CTA)

// ---------------- scratch (__device__ globals; no allocs) ----------------
__device__ float g_a1[Bc * Nc * Nc];
__device__ float g_a2[Bc * Nc * Nc];
__device__ float g_rs1[Bc * Nc];
__device__ float g_rs2[Bc * Nc];
__device__ float g_eep[2 * Bc * Nc * 16];   // edge-enc halves
__device__ float g_x2[(size_t)Bc * 10 * 4 * Nc * 16];
__device__ float g_flat[Bc * FLATc];
__device__ float g_part2[(size_t)2 * KSPLIT * Bc * HIDc];
__device__ float g_hh[2 * Bc * HIDc];

// ---------------- helpers ----------------
__device__ __forceinline__ unsigned long long f2pk(float x, float y) {
    unsigned long long d;
    asm("mov.b64 %0, {%1, %2};" : "=l"(d) : "f"(x), "f"(y));
    return d;
}
__device__ __forceinline__ void f2un(float& x, float& y, unsigned long long v) {
    asm("mov.b64 {%0, %1}, %2;" : "=f"(x), "=f"(y) : "l"(v));
}
__device__ __forceinline__ unsigned long long fma2(unsigned long long a,
                                                   unsigned long long b,
                                                   unsigned long long c) {
    unsigned long long d;
    asm("fma.rn.f32x2 %0, %1, %2, %3;" : "=l"(d) : "l"(a), "l"(b), "l"(c));
    return d;
}
__device__ __forceinline__ void cp16(uint32_t smem_dst, const void* gsrc) {
    asm volatile("cp.async.cg.shared.global [%0], [%1], 16;\n" ::
                 "r"(smem_dst), "l"(gsrc));
}
__device__ __forceinline__ void cp4(uint32_t smem_dst, const void* gsrc) {
    asm volatile("cp.async.ca.shared.global [%0], [%1], 4;\n" ::
                 "r"(smem_dst), "l"(gsrc));
}
__device__ __forceinline__ void cp_commit() {
    asm volatile("cp.async.commit_group;\n");
}
__device__ __forceinline__ void cp_wait0() {
    asm volatile("cp.async.wait_group 0;\n" ::: "memory");
}

// ============================================================
// K1: grid (32, 3), block 512, dyn smem 128*129*4
//  y==0: adjacency normalization chain (a1, rs1, a2, rs2)
//  y==1/2: edge-encoder i-half -> g_eep[half]
// ============================================================
__global__ void __launch_bounds__(512)
k1_prep(const float* __restrict__ inp,
        const float* __restrict__ We,
        const float* __restrict__ be) {
    extern __shared__ float s_a[];       // [128][129] (y>0 uses 64 rows)
    __shared__ float s_d[128];
    __shared__ float s_we[32];
    __shared__ float s_be[16];
    __shared__ float s_part[3 * 2048];
    const int b = blockIdx.x, role = blockIdx.y, tid = threadIdx.x;
    const size_t base = (size_t)b * 30 * 128 * ROWc;

    if (role != 0) {
        // ---- edge encoder for i in [h*64, h*64+64) ----
        const int h = role - 1;
        if (tid < 32) s_we[tid] = We[tid];
        if (tid >= 32 && tid < 48) s_be[tid - 32] = be[tid - 32];
        for (int idx = tid; idx < 64 * 128; idx += 512) {
            int i = idx >> 7, j = idx & 127;
            s_a[i * 129 + j] = inp[base + (size_t)(h * 64 + i) * ROWc + j];
        }
        __syncthreads();
        const int j = tid & 127;
        const int q = tid >> 7;
        float acc[16];
#pragma unroll
        for (int f = 0; f < 16; f++) acc[f] = 0.0f;
#pragma unroll 4
        for (int il = q * 16; il < q * 16 + 16; il++) {
            float a = s_a[il * 129 + j];
            const float* ep =
                inp + base + (size_t)(h * 64 + il) * ROWc + 128 + 2 * j;
            float e0 = ep[0], e1 = ep[1];
#pragma unroll
            for (int f = 0; f < 16; f++) {
                float v = fmaf(e0, s_we[f], fmaf(e1, s_we[16 + f], s_be[f]));
                v = LEAKY(v);
                acc[f] = fmaf(v, a, acc[f]);
            }
        }
        if (q) {
#pragma unroll
            for (int f = 0; f < 16; f++)
                s_part[(q - 1) * 2048 + j * 16 + f] = acc[f];
        }
        __syncthreads();
        if (q == 0) {
#pragma unroll
            for (int f = 0; f < 16; f++)
                g_eep[h * 65536 + (b * 128 + j) * 16 + f] =
                    acc[f] + s_part[j * 16 + f] + s_part[2048 + j * 16 + f] +
                    s_part[4096 + j * 16 + f];
        }
        return;
    }

    // ---- role 0: adjacency chain ----
    for (int idx = tid; idx < 128 * 128; idx += 512) {
        int i = idx >> 7, j = idx & 127;
        s_a[i * 129 + j] = inp[base + (size_t)i * ROWc + j];
    }
    __syncthreads();
    {
        const int i = tid & 127, q = tid >> 7;
        float p = 0.0f;
        for (int j = q * 32; j < q * 32 + 32; j++)
            p += (j == i) ? 1.0f : s_a[i * 129 + j];
        s_part[q * 128 + i] = p;
        __syncthreads();
        if (tid < 128) {
            float s = s_part[tid] + s_part[128 + tid] + s_part[256 + tid] +
                      s_part[384 + tid];
            s_d[tid] = 1.0f / sqrtf(fmaxf(s, 1.0f));
        }
        __syncthreads();
    }
    for (int idx = tid; idx < 128 * 128; idx += 512) {
        int i = idx >> 7, j = idx & 127;
        float a0 = (i == j) ? 1.0f : s_a[i * 129 + j];
        float v = s_d[i] * a0 * s_d[j];
        s_a[i * 129 + j] = v;
        g_a1[b * 16384 + idx] = v;
    }
    __syncthreads();
    {
        const int i = tid & 127, q = tid >> 7;
        float p = 0.0f;
        for (int j = q * 32; j < q * 32 + 32; j++) p += s_a[i * 129 + j];
        s_part[q * 128 + i] = p;
        __syncthreads();
        if (tid < 128) {
            float s = s_part[tid] + s_part[128 + tid] + s_part[256 + tid] +
                      s_part[384 + tid];
            g_rs1[b * 128 + tid] = s;
            s_d[tid] = 1.0f / sqrtf(fmaxf(s, 1.0f));
        }
        __syncthreads();
    }
    for (int idx = tid; idx < 128 * 128; idx += 512) {
        int i = idx >> 7, j = idx & 127;
        float v = s_d[i] * s_a[i * 129 + j] * s_d[j];
        s_a[i * 129 + j] = v;
        g_a2[b * 16384 + idx] = v;
    }
    __syncthreads();
    {
        const int i = tid & 127, q = tid >> 7;
        float p = 0.0f;
        for (int j = q * 32; j < q * 32 + 32; j++) p += s_a[i * 129 + j];
        s_part[q * 128 + i] = p;
        __syncthreads();
        if (tid < 128)
            g_rs2[b * 128 + tid] = s_part[tid] + s_part[128 + tid] +
                                   s_part[256 + tid] + s_part[384 + tid];
    }
}

// ============================================================
// K2: per-(b,t) GCN, 512 threads, f32x2 packed math,
// a1/a2 loads overlapped via cp.async.
// grid (32,10), block 512, dynamic smem = 128*129*4
// ============================================================
__global__ void __launch_bounds__(512)
k2_gcn(const float* __restrict__ inp,
       const float* __restrict__ Wn,
       const float* __restrict__ bn,
       const float* __restrict__ Wg,
       const float* __restrict__ bgl,
       const float* __restrict__ gb) {
    extern __shared__ float s_a[];       // [128][129]
    __shared__ float s_xs[2048];
    __shared__ float s_z[2048];
    __shared__ float s_wgT[2048];        // [l][c][o][f]
    __shared__ float s_bgl[128];
    __shared__ float s_gb[64];
    __shared__ float s_wn[80];
    __shared__ float s_bn[16];
    __shared__ float s_rs[256];

    const int b = blockIdx.x, t = blockIdx.y, tid = threadIdx.x;
    const uint32_t sa_base = (uint32_t)__cvta_generic_to_shared(s_a);

    for (int idx = tid; idx < 16384; idx += 512) {
        int i = idx >> 7, j = idx & 127;
        cp4(sa_base + (uint32_t)(i * 129 + j) * 4, &g_a1[b * 16384 + idx]);
    }
    cp_commit();

    for (int i = tid; i < 2048; i += 512) {
        int o = i & 15, f = (i >> 4) & 15, lc = i >> 8;
        s_wgT[(lc * 16 + o) * 16 + f] = Wg[i];
    }
    if (tid < 128) s_bgl[tid] = bgl[tid];
    if (tid < 64) s_gb[tid] = gb[tid];
    if (tid < 80) s_wn[tid] = Wn[tid];
    if (tid < 16) s_bn[tid] = bn[tid];
    if (tid < 128) s_rs[tid] = g_rs1[b * 128 + tid];
    if (tid >= 128 && tid < 256) s_rs[tid] = g_rs2[b * 128 + tid - 128];
    __syncthreads();

    const int n = tid & 127;
    const int f0 = (tid >> 7) * 4;

    // xs = edge_enc(sum of halves) + sum_v leaky(node@Wn + bn)
    {
        float acc[4];
        const float* e0 = &g_eep[(b * 128 + n) * 16 + f0];
        const float* e1 = &g_eep[65536 + (b * 128 + n) * 16 + f0];
#pragma unroll
        for (int f = 0; f < 4; f++) acc[f] = e0[f] + e1[f];
#pragma unroll
        for (int v = 0; v < 3; v++) {
            const float* np =
                inp + ((size_t)(b * 30 + t * 3 + v) * 128 + n) * ROWc + 384;
            float nk0 = np[0], nk1 = np[1], nk2 = np[2], nk3 = np[3], nk4 = np[4];
#pragma unroll
            for (int f = 0; f < 4; f++) {
                int fc = f0 + f;
                float s = s_bn[fc];
                s = fmaf(nk0, s_wn[fc], s);
                s = fmaf(nk1, s_wn[16 + fc], s);
                s = fmaf(nk2, s_wn[32 + fc], s);
                s = fmaf(nk3, s_wn[48 + fc], s);
                s = fmaf(nk4, s_wn[64 + fc], s);
                acc[f] += LEAKY(s);
            }
        }
        *(float4*)&s_xs[n * 16 + f0] = make_float4(acc[0], acc[1], acc[2], acc[3]);
    }
    cp_wait0();
    __syncthreads();

    // z1 = a1 @ xs
    {
        unsigned long long za0 = 0ULL, za1 = 0ULL;
#pragma unroll 8
        for (int m = 0; m < 128; m++) {
            float a = s_a[n * 129 + m];
            unsigned long long ap = f2pk(a, a);
            ulonglong2 x = *(const ulonglong2*)&s_xs[m * 16 + f0];
            za0 = fma2(ap, x.x, za0);
            za1 = fma2(ap, x.y, za1);
        }
        ulonglong2 zo; zo.x = za0; zo.y = za1;
        *(ulonglong2*)&s_z[n * 16 + f0] = zo;
    }
    __syncthreads();

    // a2 copy overlaps layer-1 mix
    for (int idx = tid; idx < 16384; idx += 512) {
        int i = idx >> 7, j = idx & 127;
        cp4(sa_base + (uint32_t)(i * 129 + j) * 4, &g_a2[b * 16384 + idx]);
    }
    cp_commit();

    // layer-1 channel mix
    {
        unsigned long long zp[8];
        ulonglong2 q0 = *(const ulonglong2*)&s_z[n * 16];
        ulonglong2 q1 = *(const ulonglong2*)&s_z[n * 16 + 4];
        ulonglong2 q2 = *(const ulonglong2*)&s_z[n * 16 + 8];
        ulonglong2 q3 = *(const ulonglong2*)&s_z[n * 16 + 12];
        zp[0] = q0.x; zp[1] = q0.y; zp[2] = q1.x; zp[3] = q1.y;
        zp[4] = q2.x; zp[5] = q2.y; zp[6] = q3.x; zp[7] = q3.y;
        float rs4 = 4.0f * s_rs[n];
        float outv[4];
#pragma unroll
        for (int o = 0; o < 4; o++) {
            int oc = f0 + o;
            float sum = 0.0f;
#pragma unroll
            for (int c = 0; c < 4; c++) {
                const unsigned long long* wp =
                    (const unsigned long long*)&s_wgT[(c * 16 + oc) * 16];
                unsigned long long a2v = 0ULL;
#pragma unroll
                for (int i = 0; i < 8; i++) a2v = fma2(zp[i], wp[i], a2v);
                float ux, uy; f2un(ux, uy, a2v);
                float u = ux + uy + fmaf(rs4, s_bgl[c * 16 + oc], s_gb[c * 16 + oc]);
                sum += LEAKY(u);
            }
            outv[o] = sum;
        }
        *(float4*)&s_xs[n * 16 + f0] =
            make_float4(outv[0], outv[1], outv[2], outv[3]);
    }
    cp_wait0();
    __syncthreads();

    // z2 = a2 @ xs2
    {
        unsigned long long za0 = 0ULL, za1 = 0ULL;
#pragma unroll 8
        for (int m = 0; m < 128; m++) {
            float a = s_a[n * 129 + m];
            unsigned long long ap = f2pk(a, a);
            ulonglong2 x = *(const ulonglong2*)&s_xs[m * 16 + f0];
            za0 = fma2(ap, x.x, za0);
            za1 = fma2(ap, x.y, za1);
        }
        ulonglong2 zo; zo.x = za0; zo.y = za1;
        *(ulonglong2*)&s_z[n * 16 + f0] = zo;
    }
    __syncthreads();

    // layer-2 channel mix -> g_x2 (float4 stores)
    {
        unsigned long long zp[8];
        ulonglong2 q0 = *(const ulonglong2*)&s_z[n * 16];
        ulonglong2 q1 = *(const ulonglong2*)&s_z[n * 16 + 4];
        ulonglong2 q2 = *(const ulonglong2*)&s_z[n * 16 + 8];
        ulonglong2 q3 = *(const ulonglong2*)&s_z[n * 16 + 12];
        zp[0] = q0.x; zp[1] = q0.y; zp[2] = q1.x; zp[3] = q1.y;
        zp[4] = q2.x; zp[5] = q2.y; zp[6] = q3.x; zp[7] = q3.y;
        float rs4 = 4.0f * s_rs[128 + n];
        size_t obase = ((size_t)(b * 10 + t) * 4) * 2048 + n * 16 + f0;
#pragma unroll
        for (int c = 0; c < 4; c++) {
            float ov[4];
#pragma unroll
            for (int o = 0; o < 4; o++) {
                int oc = f0 + o;
                const unsigned long long* wp =
                    (const unsigned long long*)&s_wgT[((4 + c) * 16 + oc) * 16];
                unsigned long long a2v = 0ULL;
#pragma unroll
                for (int i = 0; i < 8; i++) a2v = fma2(zp[i], wp[i], a2v);
                float ux, uy; f2un(ux, uy, a2v);
                float u = ux + uy +
                          fmaf(rs4, s_bgl[64 + c * 16 + oc], s_gb[c * 16 + oc]);
                ov[o] = LEAKY(u);
            }
            *(float4*)&g_x2[obase + c * 2048] =
                make_float4(ov[0], ov[1], ov[2], ov[3]);
        }
    }
}

// ============================================================
// K3: reduce over t -> flat (float4). grid 256, block 256
// ============================================================
__global__ void k3_reduce() {
    int idx4 = blockIdx.x * 256 + threadIdx.x;   // 0..65535
    int b = idx4 >> 11;
    int j4 = idx4 & 2047;
    const float4* p = (const float4*)&g_x2[(size_t)b * 10 * 8192] + j4;
    float4 s = make_float4(0.f, 0.f, 0.f, 0.f);
#pragma unroll
    for (int t = 0; t < 10; t++) {
        float4 v = p[t * 2048];
        s.x += v.x; s.y += v.y; s.z += v.z; s.w += v.w;
    }
    ((float4*)g_flat)[idx4] = s;
}

// ============================================================
// K4 (v6, proven): flat(32x8192) @ W(8192x2048) x2 heads.
// Warp = 8-row group; flat stage-tile in REGISTERS (shfl broadcast),
// W double-buffered via cp.async. KSPLIT=16 -> 512 k per CTA, 32 stages.
// grid (16, 16, 2) = 512 CTAs, block 128, 6 CTAs/SM.
// ============================================================
__global__ void __launch_bounds__(128, 6)
k4_gemm(const float* __restrict__ Wc1, const float* __restrict__ Wa1) {
    __shared__ float s_w[2][16][128];     // 16 KB
    const int tid = threadIdx.x;
    const int head = blockIdx.z;
    const float* __restrict__ W = head ? Wa1 : Wc1;
    const int colbase = blockIdx.x * 128;
    const int warp = tid >> 5, lane = tid & 31;
    const int rowbase = warp * 8;
    const int kbase = blockIdx.y * 512;

    // this lane holds flat[rowbase + (lane>>2)][k0 + (lane&3)*4 .. +3]
    const int fr = rowbase + (lane >> 2);
    const int fq = (lane & 3) * 4;

    const uint32_t sw0 = (uint32_t)__cvta_generic_to_shared(&s_w[0][0][0]);
    const uint32_t sw1 = (uint32_t)__cvta_generic_to_shared(&s_w[1][0][0]);

    unsigned long long acc[8][2];
#pragma unroll
    for (int r = 0; r < 8; r++) { acc[r][0] = 0ULL; acc[r][1] = 0ULL; }

    // prologue: stage-0 W tile
    {
#pragma unroll
        for (int i = 0; i < 4; i++) {
            int idx = tid + i * 128;               // 0..511
            int kr = idx >> 5, cq = idx & 31;
            cp16(sw0 + (uint32_t)(kr * 128 + cq * 4) * 4,
                 &W[(size_t)(kbase + kr) * 2048 + colbase + cq * 4]);
        }
        cp_commit();
    }
    float4 fcur = *(const float4*)&g_flat[fr * 8192 + kbase + fq];
    float4 fnext = *(const float4*)&g_flat[fr * 8192 + kbase + 16 + fq];

    for (int s = 0; s < 32; s++) {
        const int b = s & 1;
        cp_wait0();
        __syncthreads();
        if (s < 31) {
            const uint32_t swn = b ? sw0 : sw1;
            const int kn = kbase + (s + 1) * 16;
#pragma unroll
            for (int i = 0; i < 4; i++) {
                int idx = tid + i * 128;
                int kr = idx >> 5, cq = idx & 31;
                cp16(swn + (uint32_t)(kr * 128 + cq * 4) * 4,
                     &W[(size_t)(kn + kr) * 2048 + colbase + cq * 4]);
            }
            cp_commit();
        }
        float fc0 = fcur.x, fc1 = fcur.y, fc2 = fcur.z, fc3 = fcur.w;
#pragma unroll
        for (int kp = 0; kp < 8; kp++) {
            ulonglong2 w0 = *(const ulonglong2*)&s_w[b][kp * 2][lane * 4];
            ulonglong2 w1 = *(const ulonglong2*)&s_w[b][kp * 2 + 1][lane * 4];
            const bool hi = (kp & 1);
#pragma unroll
            for (int r = 0; r < 8; r++) {
                const int src = r * 4 + (kp >> 1);
                float vk = __shfl_sync(0xffffffffu, hi ? fc2 : fc0, src);
                float vk1 = __shfl_sync(0xffffffffu, hi ? fc3 : fc1, src);
                unsigned long long dk = f2pk(vk, vk);
                unsigned long long dk1 = f2pk(vk1, vk1);
                acc[r][0] = fma2(dk, w0.x, acc[r][0]);
                acc[r][1] = fma2(dk, w0.y, acc[r][1]);
                acc[r][0] = fma2(dk1, w1.x, acc[r][0]);
                acc[r][1] = fma2(dk1, w1.y, acc[r][1]);
            }
        }
        fcur = fnext;
        if (s < 30)
            fnext = *(const float4*)&g_flat[fr * 8192 + kbase + (s + 2) * 16 + fq];
    }

    const size_t base = ((size_t)(head * KSPLIT + blockIdx.y)) * 65536;
    const int gcol = colbase + lane * 4;
#pragma unroll
    for (int r = 0; r < 8; r++) {
        float4 o;
        f2un(o.x, o.y, acc[r][0]);
        f2un(o.z, o.w, acc[r][1]);
        *(float4*)&g_part2[base + (size_t)(rowbase + r) * 2048 + gcol] = o;
    }
}

// ============================================================
// K5a: reduce K-split partials + bias + leaky (float4)
// grid (64, 2), block 256
// ============================================================
__global__ void k5a_act(const float* __restrict__ bc1,
                        const float* __restrict__ ba1) {
    const int head = blockIdx.y;
    const int i4 = blockIdx.x * 256 + threadIdx.x;   // 0..16383
    const int col4 = i4 & 511;
    float4 s = ((const float4*)(head ? ba1 : bc1))[col4];
    const float4* p = (const float4*)&g_part2[(size_t)head * KSPLIT * 65536];
#pragma unroll
    for (int pi = 0; pi < KSPLIT; pi++) {
        float4 v = p[(size_t)pi * 16384 + i4];
        s.x += v.x; s.y += v.y; s.z += v.z; s.w += v.w;
    }
    s.x = LEAKY(s.x); s.y = LEAKY(s.y); s.z = LEAKY(s.z); s.w = LEAKY(s.w);
    ((float4*)g_hh)[head * 16384 + i4] = s;
}

// ============================================================
// K5b: small heads, per-head CTAs + W2 prefetch.
// grid (32, 2), block 256
// ============================================================
__global__ void k5b_heads(const float* __restrict__ Wc2,
                          const float* __restrict__ bc2,
                          const float* __restrict__ Wc3,
                          const float* __restrict__ bc3,
                          const float* __restrict__ Wa2,
                          const float* __restrict__ ba2,
                          float* __restrict__ out) {
    __shared__ float s_h[2048];
    __shared__ float s_w[256 * 17];
    __shared__ float s_r[16];
    const int b = blockIdx.x, head = blockIdx.y, tid = threadIdx.x;
    const float* __restrict__ W2 = head ? Wa2 : Wc2;
    const float* __restrict__ b2 = head ? ba2 : bc2;

    {
        const float4* hs = (const float4*)&g_hh[head * 65536 + b * 2048];
        ((float4*)s_h)[tid] = hs[tid];
        ((float4*)s_h)[tid + 256] = hs[tid + 256];
    }
    const int w = tid >> 5, lane = tid & 31;
    float ps[2] = {0.0f, 0.0f};

    float rv[16];
#pragma unroll
    for (int i = 0; i < 16; i++) rv[i] = W2[tid + i * 256];

    for (int c = 0; c < 8; c++) {
        __syncthreads();
#pragma unroll
        for (int i = 0; i < 16; i++) {
            int idx = tid + i * 256;
            s_w[(idx >> 4) * 17 + (idx & 15)] = rv[i];
        }
        __syncthreads();
        if (c < 7) {
#pragma unroll
            for (int i = 0; i < 16; i++)
                rv[i] = W2[(c + 1) * 4096 + tid + i * 256];
        }
#pragma unroll
        for (int dd = 0; dd < 2; dd++) {
            const int f = w + dd * 8;
            float s = 0.0f;
#pragma unroll
            for (int ki = 0; ki < 8; ki++) {
                int k = ki * 32 + lane;
                s = fmaf(s_h[c * 256 + k], s_w[k * 17 + f], s);
            }
            ps[dd] += s;
        }
    }
#pragma unroll
    for (int dd = 0; dd < 2; dd++) {
        float s = ps[dd];
#pragma unroll
        for (int off = 16; off; off >>= 1) s += __shfl_down_sync(0xffffffffu, s, off);
        if (lane == 0) {
            int f = w + dd * 8;
            float v = s + b2[f];
            s_r[f] = LEAKY(v);
        }
    }
    __syncthreads();
    if (head == 0) {
        if (tid == 0) {
            float cr = bc3[0];
#pragma unroll
            for (int f = 0; f < 16; f++) cr = fmaf(s_r[f], Wc3[f], cr);
            out[b] = cr;
        }
    } else {
        if (tid < 16) out[32 + b * 16 + tid] = s_r[tid];
    }
}

// ============================================================
extern "C" void kernel_launch(void* const* d_in, const int* in_sizes, int n_in,
                              void* d_out, int out_size) {
    (void)in_sizes; (void)n_in; (void)out_size;
    const float* inp = (const float*)d_in[0];
    const float* We  = (const float*)d_in[1];
    const float* be  = (const float*)d_in[2];
    const float* Wn  = (const float*)d_in[3];
    const float* bn  = (const float*)d_in[4];
    const float* Wg  = (const float*)d_in[5];
    const float* bgl = (const float*)d_in[6];
    const float* gb  = (const float*)d_in[7];
    const float* Wc1 = (const float*)d_in[8];
    const float* bc1 = (const float*)d_in[9];
    const float* Wc2 = (const float*)d_in[10];
    const float* bc2 = (const float*)d_in[11];
    const float* Wc3 = (const float*)d_in[12];
    const float* bc3 = (const float*)d_in[13];
    const float* Wa1 = (const float*)d_in[14];
    const float* ba1 = (const float*)d_in[15];
    const float* Wa2 = (const float*)d_in[16];
    const float* ba2 = (const float*)d_in[17];

    const int dyn = 128 * 129 * 4;  // 66048 B
    cudaFuncSetAttribute(k1_prep, cudaFuncAttributeMaxDynamicSharedMemorySize, dyn);
    cudaFuncSetAttribute(k2_gcn, cudaFuncAttributeMaxDynamicSharedMemorySize, dyn);

    k1_prep<<<dim3(32, 3), 512, dyn>>>(inp, We, be);
    k2_gcn<<<dim3(32, 10), 512, dyn>>>(inp, Wn, bn, Wg, bgl, gb);
    k3_reduce<<<256, 256>>>();
    k4_gemm<<<dim3(16, KSPLIT, 2), 128>>>(Wc1, Wa1);
    k5a_act<<<dim3(64, 2), 256>>>(bc1, ba1);
    k5b_heads<<<dim3(32, 2), 256>>>(Wc2, bc2, Wc3, bc3, Wa2, ba2, (float*)d_out);
}

// round 11
// speedup vs baseline: 1.0865x; 1.0423x over previous
#include <cuda_runtime.h>
#include <cstdint>
#include <cstddef>

// ---------------- problem dims ----------------
// B=32, T=10, NOV=3, N=128, F=16, NF=5, EF=2, C=4, SL=2, HID=2048
#define LEAKY(x) ((x) > 0.0f ? (x) : 0.01f * (x))

constexpr int Bc = 32;
constexpr int Nc = 128;
constexpr int HIDc = 2048;
constexpr int ROWc = 389;      // 3N+NF
constexpr int FLATc = 8192;    // C*N*F
constexpr int KSPLIT = 32;     // k4 K-split factor (256 k per CTA)
constexpr int PITCH = 132;     // k2 s_a pitch (16B-aligned rows, conflict-free)

// ---------------- scratch (__device__ globals; no allocs) ----------------
__device__ float g_a1[Bc * Nc * Nc];
__device__ float g_a2[Bc * Nc * Nc];
__device__ float g_rs1[Bc * Nc];
__device__ float g_rs2[Bc * Nc];
__device__ float g_eep[2 * Bc * Nc * 16];   // edge-enc halves
__device__ float g_x2[(size_t)Bc * 10 * 4 * Nc * 16];
__device__ float g_flat[Bc * FLATc];
__device__ float g_part2[(size_t)2 * KSPLIT * Bc * HIDc];
__device__ float g_hh[2 * Bc * HIDc];

// ---------------- helpers ----------------
__device__ __forceinline__ unsigned long long f2pk(float x, float y) {
    unsigned long long d;
    asm("mov.b64 %0, {%1, %2};" : "=l"(d) : "f"(x), "f"(y));
    return d;
}
__device__ __forceinline__ void f2un(float& x, float& y, unsigned long long v) {
    asm("mov.b64 {%0, %1}, %2;" : "=f"(x), "=f"(y) : "l"(v));
}
__device__ __forceinline__ unsigned long long fma2(unsigned long long a,
                                                   unsigned long long b,
                                                   unsigned long long c) {
    unsigned long long d;
    asm("fma.rn.f32x2 %0, %1, %2, %3;" : "=l"(d) : "l"(a), "l"(b), "l"(c));
    return d;
}
__device__ __forceinline__ void cp16(uint32_t smem_dst, const void* gsrc) {
    asm volatile("cp.async.cg.shared.global [%0], [%1], 16;\n" ::
                 "r"(smem_dst), "l"(gsrc));
}
__device__ __forceinline__ void cp4(uint32_t smem_dst, const void* gsrc) {
    asm volatile("cp.async.ca.shared.global [%0], [%1], 4;\n" ::
                 "r"(smem_dst), "l"(gsrc));
}
__device__ __forceinline__ void cp_commit() {
    asm volatile("cp.async.commit_group;\n");
}
__device__ __forceinline__ void cp_wait0() {
    asm volatile("cp.async.wait_group 0;\n" ::: "memory");
}

// ============================================================
// K1: grid (32, 3), block 512, dyn smem 128*129*4
//  y==0: adjacency normalization chain (a1, rs1, a2, rs2)
//  y==1/2: edge-encoder i-half -> g_eep[half]
// ============================================================
__global__ void __launch_bounds__(512)
k1_prep(const float* __restrict__ inp,
        const float* __restrict__ We,
        const float* __restrict__ be) {
    extern __shared__ float s_a[];       // [128][129] (y>0 uses 64 rows)
    __shared__ float s_d[128];
    __shared__ float s_we[32];
    __shared__ float s_be[16];
    __shared__ float s_part[3 * 2048];
    const int b = blockIdx.x, role = blockIdx.y, tid = threadIdx.x;
    const size_t base = (size_t)b * 30 * 128 * ROWc;

    if (role != 0) {
        // ---- edge encoder for i in [h*64, h*64+64) ----
        const int h = role - 1;
        if (tid < 32) s_we[tid] = We[tid];
        if (tid >= 32 && tid < 48) s_be[tid - 32] = be[tid - 32];
        for (int idx = tid; idx < 64 * 128; idx += 512) {
            int i = idx >> 7, j = idx & 127;
            s_a[i * 129 + j] = inp[base + (size_t)(h * 64 + i) * ROWc + j];
        }
        __syncthreads();
        const int j = tid & 127;
        const int q = tid >> 7;
        float acc[16];
#pragma unroll
        for (int f = 0; f < 16; f++) acc[f] = 0.0f;
#pragma unroll 4
        for (int il = q * 16; il < q * 16 + 16; il++) {
            float a = s_a[il * 129 + j];
            const float* ep =
                inp + base + (size_t)(h * 64 + il) * ROWc + 128 + 2 * j;
            float e0 = ep[0], e1 = ep[1];
#pragma unroll
            for (int f = 0; f < 16; f++) {
                float v = fmaf(e0, s_we[f], fmaf(e1, s_we[16 + f], s_be[f]));
                v = LEAKY(v);
                acc[f] = fmaf(v, a, acc[f]);
            }
        }
        if (q) {
#pragma unroll
            for (int f = 0; f < 16; f++)
                s_part[(q - 1) * 2048 + j * 16 + f] = acc[f];
        }
        __syncthreads();
        if (q == 0) {
#pragma unroll
            for (int f = 0; f < 16; f++)
                g_eep[h * 65536 + (b * 128 + j) * 16 + f] =
                    acc[f] + s_part[j * 16 + f] + s_part[2048 + j * 16 + f] +
                    s_part[4096 + j * 16 + f];
        }
        return;
    }

    // ---- role 0: adjacency chain ----
    for (int idx = tid; idx < 128 * 128; idx += 512) {
        int i = idx >> 7, j = idx & 127;
        s_a[i * 129 + j] = inp[base + (size_t)i * ROWc + j];
    }
    __syncthreads();
    {
        const int i = tid & 127, q = tid >> 7;
        float p = 0.0f;
        for (int j = q * 32; j < q * 32 + 32; j++)
            p += (j == i) ? 1.0f : s_a[i * 129 + j];
        s_part[q * 128 + i] = p;
        __syncthreads();
        if (tid < 128) {
            float s = s_part[tid] + s_part[128 + tid] + s_part[256 + tid] +
                      s_part[384 + tid];
            s_d[tid] = 1.0f / sqrtf(fmaxf(s, 1.0f));
        }
        __syncthreads();
    }
    for (int idx = tid; idx < 128 * 128; idx += 512) {
        int i = idx >> 7, j = idx & 127;
        float a0 = (i == j) ? 1.0f : s_a[i * 129 + j];
        float v = s_d[i] * a0 * s_d[j];
        s_a[i * 129 + j] = v;
        g_a1[b * 16384 + idx] = v;
    }
    __syncthreads();
    {
        const int i = tid & 127, q = tid >> 7;
        float p = 0.0f;
        for (int j = q * 32; j < q * 32 + 32; j++) p += s_a[i * 129 + j];
        s_part[q * 128 + i] = p;
        __syncthreads();
        if (tid < 128) {
            float s = s_part[tid] + s_part[128 + tid] + s_part[256 + tid] +
                      s_part[384 + tid];
            g_rs1[b * 128 + tid] = s;
            s_d[tid] = 1.0f / sqrtf(fmaxf(s, 1.0f));
        }
        __syncthreads();
    }
    for (int idx = tid; idx < 128 * 128; idx += 512) {
        int i = idx >> 7, j = idx & 127;
        float v = s_d[i] * s_a[i * 129 + j] * s_d[j];
        s_a[i * 129 + j] = v;
        g_a2[b * 16384 + idx] = v;
    }
    __syncthreads();
    {
        const int i = tid & 127, q = tid >> 7;
        float p = 0.0f;
        for (int j = q * 32; j < q * 32 + 32; j++) p += s_a[i * 129 + j];
        s_part[q * 128 + i] = p;
        __syncthreads();
        if (tid < 128)
            g_rs2[b * 128 + tid] = s_part[tid] + s_part[128 + tid] +
                                   s_part[256 + tid] + s_part[384 + tid];
    }
}

// ============================================================
// K2: per-(b,t) GCN, 512 threads, f32x2 packed math,
// a1/a2 loads overlapped via cp.async; s_a pitch 132 for
// vectorized (LDS.128) a-row reads in the z matmuls.
// grid (32,10), block 512, dynamic smem = 128*132*4
// ============================================================
__global__ void __launch_bounds__(512)
k2_gcn(const float* __restrict__ inp,
       const float* __restrict__ Wn,
       const float* __restrict__ bn,
       const float* __restrict__ Wg,
       const float* __restrict__ bgl,
       const float* __restrict__ gb) {
    extern __shared__ float s_a[];       // [128][PITCH=132]
    __shared__ float s_xs[2048];
    __shared__ float s_z[2048];
    __shared__ float s_wgT[2048];        // [l][c][o][f]
    __shared__ float s_bgl[128];
    __shared__ float s_gb[64];
    __shared__ float s_wn[80];
    __shared__ float s_bn[16];
    __shared__ float s_rs[256];

    const int b = blockIdx.x, t = blockIdx.y, tid = threadIdx.x;
    const uint32_t sa_base = (uint32_t)__cvta_generic_to_shared(s_a);

    for (int idx = tid; idx < 16384; idx += 512) {
        int i = idx >> 7, j = idx & 127;
        cp4(sa_base + (uint32_t)(i * PITCH + j) * 4, &g_a1[b * 16384 + idx]);
    }
    cp_commit();

    for (int i = tid; i < 2048; i += 512) {
        int o = i & 15, f = (i >> 4) & 15, lc = i >> 8;
        s_wgT[(lc * 16 + o) * 16 + f] = Wg[i];
    }
    if (tid < 128) s_bgl[tid] = bgl[tid];
    if (tid < 64) s_gb[tid] = gb[tid];
    if (tid < 80) s_wn[tid] = Wn[tid];
    if (tid < 16) s_bn[tid] = bn[tid];
    if (tid < 128) s_rs[tid] = g_rs1[b * 128 + tid];
    if (tid >= 128 && tid < 256) s_rs[tid] = g_rs2[b * 128 + tid - 128];
    __syncthreads();

    const int n = tid & 127;
    const int f0 = (tid >> 7) * 4;

    // xs = edge_enc(sum of halves) + sum_v leaky(node@Wn + bn)
    {
        float acc[4];
        const float* e0 = &g_eep[(b * 128 + n) * 16 + f0];
        const float* e1 = &g_eep[65536 + (b * 128 + n) * 16 + f0];
#pragma unroll
        for (int f = 0; f < 4; f++) acc[f] = e0[f] + e1[f];
#pragma unroll
        for (int v = 0; v < 3; v++) {
            const float* np =
                inp + ((size_t)(b * 30 + t * 3 + v) * 128 + n) * ROWc + 384;
            float nk0 = np[0], nk1 = np[1], nk2 = np[2], nk3 = np[3], nk4 = np[4];
#pragma unroll
            for (int f = 0; f < 4; f++) {
                int fc = f0 + f;
                float s = s_bn[fc];
                s = fmaf(nk0, s_wn[fc], s);
                s = fmaf(nk1, s_wn[16 + fc], s);
                s = fmaf(nk2, s_wn[32 + fc], s);
                s = fmaf(nk3, s_wn[48 + fc], s);
                s = fmaf(nk4, s_wn[64 + fc], s);
                acc[f] += LEAKY(s);
            }
        }
        *(float4*)&s_xs[n * 16 + f0] = make_float4(acc[0], acc[1], acc[2], acc[3]);
    }
    cp_wait0();
    __syncthreads();

    // z1 = a1 @ xs  (vectorized a-row loads)
    {
        unsigned long long za0 = 0ULL, za1 = 0ULL;
        const float* arow = &s_a[n * PITCH];
#pragma unroll 4
        for (int m4 = 0; m4 < 32; m4++) {
            float4 a4 = *(const float4*)&arow[m4 * 4];
#pragma unroll
            for (int j = 0; j < 4; j++) {
                float a = (j == 0) ? a4.x : (j == 1) ? a4.y : (j == 2) ? a4.z : a4.w;
                unsigned long long ap = f2pk(a, a);
                ulonglong2 x = *(const ulonglong2*)&s_xs[(m4 * 4 + j) * 16 + f0];
                za0 = fma2(ap, x.x, za0);
                za1 = fma2(ap, x.y, za1);
            }
        }
        ulonglong2 zo; zo.x = za0; zo.y = za1;
        *(ulonglong2*)&s_z[n * 16 + f0] = zo;
    }
    __syncthreads();

    // a2 copy overlaps layer-1 mix
    for (int idx = tid; idx < 16384; idx += 512) {
        int i = idx >> 7, j = idx & 127;
        cp4(sa_base + (uint32_t)(i * PITCH + j) * 4, &g_a2[b * 16384 + idx]);
    }
    cp_commit();

    // layer-1 channel mix
    {
        unsigned long long zp[8];
        ulonglong2 q0 = *(const ulonglong2*)&s_z[n * 16];
        ulonglong2 q1 = *(const ulonglong2*)&s_z[n * 16 + 4];
        ulonglong2 q2 = *(const ulonglong2*)&s_z[n * 16 + 8];
        ulonglong2 q3 = *(const ulonglong2*)&s_z[n * 16 + 12];
        zp[0] = q0.x; zp[1] = q0.y; zp[2] = q1.x; zp[3] = q1.y;
        zp[4] = q2.x; zp[5] = q2.y; zp[6] = q3.x; zp[7] = q3.y;
        float rs4 = 4.0f * s_rs[n];
        float outv[4];
#pragma unroll
        for (int o = 0; o < 4; o++) {
            int oc = f0 + o;
            float sum = 0.0f;
#pragma unroll
            for (int c = 0; c < 4; c++) {
                const unsigned long long* wp =
                    (const unsigned long long*)&s_wgT[(c * 16 + oc) * 16];
                unsigned long long a2v = 0ULL;
#pragma unroll
                for (int i = 0; i < 8; i++) a2v = fma2(zp[i], wp[i], a2v);
                float ux, uy; f2un(ux, uy, a2v);
                float u = ux + uy + fmaf(rs4, s_bgl[c * 16 + oc], s_gb[c * 16 + oc]);
                sum += LEAKY(u);
            }
            outv[o] = sum;
        }
        *(float4*)&s_xs[n * 16 + f0] =
            make_float4(outv[0], outv[1], outv[2], outv[3]);
    }
    cp_wait0();
    __syncthreads();

    // z2 = a2 @ xs2  (vectorized a-row loads)
    {
        unsigned long long za0 = 0ULL, za1 = 0ULL;
        const float* arow = &s_a[n * PITCH];
#pragma unroll 4
        for (int m4 = 0; m4 < 32; m4++) {
            float4 a4 = *(const float4*)&arow[m4 * 4];
#pragma unroll
            for (int j = 0; j < 4; j++) {
                float a = (j == 0) ? a4.x : (j == 1) ? a4.y : (j == 2) ? a4.z : a4.w;
                unsigned long long ap = f2pk(a, a);
                ulonglong2 x = *(const ulonglong2*)&s_xs[(m4 * 4 + j) * 16 + f0];
                za0 = fma2(ap, x.x, za0);
                za1 = fma2(ap, x.y, za1);
            }
        }
        ulonglong2 zo; zo.x = za0; zo.y = za1;
        *(ulonglong2*)&s_z[n * 16 + f0] = zo;
    }
    __syncthreads();

    // layer-2 channel mix -> g_x2 (float4 stores)
    {
        unsigned long long zp[8];
        ulonglong2 q0 = *(const ulonglong2*)&s_z[n * 16];
        ulonglong2 q1 = *(const ulonglong2*)&s_z[n * 16 + 4];
        ulonglong2 q2 = *(const ulonglong2*)&s_z[n * 16 + 8];
        ulonglong2 q3 = *(const ulonglong2*)&s_z[n * 16 + 12];
        zp[0] = q0.x; zp[1] = q0.y; zp[2] = q1.x; zp[3] = q1.y;
        zp[4] = q2.x; zp[5] = q2.y; zp[6] = q3.x; zp[7] = q3.y;
        float rs4 = 4.0f * s_rs[128 + n];
        size_t obase = ((size_t)(b * 10 + t) * 4) * 2048 + n * 16 + f0;
#pragma unroll
        for (int c = 0; c < 4; c++) {
            float ov[4];
#pragma unroll
            for (int o = 0; o < 4; o++) {
                int oc = f0 + o;
                const unsigned long long* wp =
                    (const unsigned long long*)&s_wgT[((4 + c) * 16 + oc) * 16];
                unsigned long long a2v = 0ULL;
#pragma unroll
                for (int i = 0; i < 8; i++) a2v = fma2(zp[i], wp[i], a2v);
                float ux, uy; f2un(ux, uy, a2v);
                float u = ux + uy +
                          fmaf(rs4, s_bgl[64 + c * 16 + oc], s_gb[c * 16 + oc]);
                ov[o] = LEAKY(u);
            }
            *(float4*)&g_x2[obase + c * 2048] =
                make_float4(ov[0], ov[1], ov[2], ov[3]);
        }
    }
}

// ============================================================
// K3: reduce over t -> flat (float4). grid 256, block 256
// ============================================================
__global__ void k3_reduce() {
    int idx4 = blockIdx.x * 256 + threadIdx.x;   // 0..65535
    int b = idx4 >> 11;
    int j4 = idx4 & 2047;
    const float4* p = (const float4*)&g_x2[(size_t)b * 10 * 8192] + j4;
    float4 s = make_float4(0.f, 0.f, 0.f, 0.f);
#pragma unroll
    for (int t = 0; t < 10; t++) {
        float4 v = p[t * 2048];
        s.x += v.x; s.y += v.y; s.z += v.z; s.w += v.w;
    }
    ((float4*)g_flat)[idx4] = s;
}

// ============================================================
// K4 (R8 v6, proven 55.4us): flat(32x8192) @ W(8192x2048) x2 heads.
// Warp = 8-row group; flat stage-tile in REGISTERS (shfl broadcast),
// W double-buffered via cp.async. KSPLIT=32 -> 256 k per CTA, 16 stages.
// grid (16, 32, 2) = 1024 CTAs, block 128, 6 CTAs/SM.
// ============================================================
__global__ void __launch_bounds__(128, 6)
k4_gemm(const float* __restrict__ Wc1, const float* __restrict__ Wa1) {
    __shared__ float s_w[2][16][128];     // 16 KB
    const int tid = threadIdx.x;
    const int head = blockIdx.z;
    const float* __restrict__ W = head ? Wa1 : Wc1;
    const int colbase = blockIdx.x * 128;
    const int warp = tid >> 5, lane = tid & 31;
    const int rowbase = warp * 8;
    const int kbase = blockIdx.y * 256;

    // this lane holds flat[rowbase + (lane>>2)][k0 + (lane&3)*4 .. +3]
    const int fr = rowbase + (lane >> 2);
    const int fq = (lane & 3) * 4;

    const uint32_t sw0 = (uint32_t)__cvta_generic_to_shared(&s_w[0][0][0]);
    const uint32_t sw1 = (uint32_t)__cvta_generic_to_shared(&s_w[1][0][0]);

    unsigned long long acc[8][2];
#pragma unroll
    for (int r = 0; r < 8; r++) { acc[r][0] = 0ULL; acc[r][1] = 0ULL; }

    // prologue: stage-0 W tile
    {
#pragma unroll
        for (int i = 0; i < 4; i++) {
            int idx = tid + i * 128;               // 0..511
            int kr = idx >> 5, cq = idx & 31;
            cp16(sw0 + (uint32_t)(kr * 128 + cq * 4) * 4,
                 &W[(size_t)(kbase + kr) * 2048 + colbase + cq * 4]);
        }
        cp_commit();
    }
    float4 fcur = *(const float4*)&g_flat[fr * 8192 + kbase + fq];
    float4 fnext = *(const float4*)&g_flat[fr * 8192 + kbase + 16 + fq];

    for (int s = 0; s < 16; s++) {
        const int b = s & 1;
        cp_wait0();
        __syncthreads();
        if (s < 15) {
            const uint32_t swn = b ? sw0 : sw1;
            const int kn = kbase + (s + 1) * 16;
#pragma unroll
            for (int i = 0; i < 4; i++) {
                int idx = tid + i * 128;
                int kr = idx >> 5, cq = idx & 31;
                cp16(swn + (uint32_t)(kr * 128 + cq * 4) * 4,
                     &W[(size_t)(kn + kr) * 2048 + colbase + cq * 4]);
            }
            cp_commit();
        }
        float fc0 = fcur.x, fc1 = fcur.y, fc2 = fcur.z, fc3 = fcur.w;
#pragma unroll
        for (int kp = 0; kp < 8; kp++) {
            ulonglong2 w0 = *(const ulonglong2*)&s_w[b][kp * 2][lane * 4];
            ulonglong2 w1 = *(const ulonglong2*)&s_w[b][kp * 2 + 1][lane * 4];
            const bool hi = (kp & 1);
#pragma unroll
            for (int r = 0; r < 8; r++) {
                const int src = r * 4 + (kp >> 1);
                float vk = __shfl_sync(0xffffffffu, hi ? fc2 : fc0, src);
                float vk1 = __shfl_sync(0xffffffffu, hi ? fc3 : fc1, src);
                unsigned long long dk = f2pk(vk, vk);
                unsigned long long dk1 = f2pk(vk1, vk1);
                acc[r][0] = fma2(dk, w0.x, acc[r][0]);
                acc[r][1] = fma2(dk, w0.y, acc[r][1]);
                acc[r][0] = fma2(dk1, w1.x, acc[r][0]);
                acc[r][1] = fma2(dk1, w1.y, acc[r][1]);
            }
        }
        fcur = fnext;
        if (s < 14)
            fnext = *(const float4*)&g_flat[fr * 8192 + kbase + (s + 2) * 16 + fq];
    }

    const size_t base = ((size_t)(head * KSPLIT + blockIdx.y)) * 65536;
    const int gcol = colbase + lane * 4;
#pragma unroll
    for (int r = 0; r < 8; r++) {
        float4 o;
        f2un(o.x, o.y, acc[r][0]);
        f2un(o.z, o.w, acc[r][1]);
        *(float4*)&g_part2[base + (size_t)(rowbase + r) * 2048 + gcol] = o;
    }
}

// ============================================================
// K5a: reduce K-split partials + bias + leaky (float4)
// grid (64, 2), block 256
// ============================================================
__global__ void k5a_act(const float* __restrict__ bc1,
                        const float* __restrict__ ba1) {
    const int head = blockIdx.y;
    const int i4 = blockIdx.x * 256 + threadIdx.x;   // 0..16383
    const int col4 = i4 & 511;
    float4 s = ((const float4*)(head ? ba1 : bc1))[col4];
    const float4* p = (const float4*)&g_part2[(size_t)head * KSPLIT * 65536];
#pragma unroll
    for (int pi = 0; pi < KSPLIT; pi++) {
        float4 v = p[(size_t)pi * 16384 + i4];
        s.x += v.x; s.y += v.y; s.z += v.z; s.w += v.w;
    }
    s.x = LEAKY(s.x); s.y = LEAKY(s.y); s.z = LEAKY(s.z); s.w = LEAKY(s.w);
    ((float4*)g_hh)[head * 16384 + i4] = s;
}

// ============================================================
// K5b: small heads, per-head CTAs + W2 prefetch.
// grid (32, 2), block 256
// ============================================================
__global__ void k5b_heads(const float* __restrict__ Wc2,
                          const float* __restrict__ bc2,
                          const float* __restrict__ Wc3,
                          const float* __restrict__ bc3,
                          const float* __restrict__ Wa2,
                          const float* __restrict__ ba2,
                          float* __restrict__ out) {
    __shared__ float s_h[2048];
    __shared__ float s_w[256 * 17];
    __shared__ float s_r[16];
    const int b = blockIdx.x, head = blockIdx.y, tid = threadIdx.x;
    const float* __restrict__ W2 = head ? Wa2 : Wc2;
    const float* __restrict__ b2 = head ? ba2 : bc2;

    {
        const float4* hs = (const float4*)&g_hh[head * 65536 + b * 2048];
        ((float4*)s_h)[tid] = hs[tid];
        ((float4*)s_h)[tid + 256] = hs[tid + 256];
    }
    const int w = tid >> 5, lane = tid & 31;
    float ps[2] = {0.0f, 0.0f};

    float rv[16];
#pragma unroll
    for (int i = 0; i < 16; i++) rv[i] = W2[tid + i * 256];

    for (int c = 0; c < 8; c++) {
        __syncthreads();
#pragma unroll
        for (int i = 0; i < 16; i++) {
            int idx = tid + i * 256;
            s_w[(idx >> 4) * 17 + (idx & 15)] = rv[i];
        }
        __syncthreads();
        if (c < 7) {
#pragma unroll
            for (int i = 0; i < 16; i++)
                rv[i] = W2[(c + 1) * 4096 + tid + i * 256];
        }
#pragma unroll
        for (int dd = 0; dd < 2; dd++) {
            const int f = w + dd * 8;
            float s = 0.0f;
#pragma unroll
            for (int ki = 0; ki < 8; ki++) {
                int k = ki * 32 + lane;
                s = fmaf(s_h[c * 256 + k], s_w[k * 17 + f], s);
            }
            ps[dd] += s;
        }
    }
#pragma unroll
    for (int dd = 0; dd < 2; dd++) {
        float s = ps[dd];
#pragma unroll
        for (int off = 16; off; off >>= 1) s += __shfl_down_sync(0xffffffffu, s, off);
        if (lane == 0) {
            int f = w + dd * 8;
            float v = s + b2[f];
            s_r[f] = LEAKY(v);
        }
    }
    __syncthreads();
    if (head == 0) {
        if (tid == 0) {
            float cr = bc3[0];
#pragma unroll
            for (int f = 0; f < 16; f++) cr = fmaf(s_r[f], Wc3[f], cr);
            out[b] = cr;
        }
    } else {
        if (tid < 16) out[32 + b * 16 + tid] = s_r[tid];
    }
}

// ============================================================
extern "C" void kernel_launch(void* const* d_in, const int* in_sizes, int n_in,
                              void* d_out, int out_size) {
    (void)in_sizes; (void)n_in; (void)out_size;
    const float* inp = (const float*)d_in[0];
    const float* We  = (const float*)d_in[1];
    const float* be  = (const float*)d_in[2];
    const float* Wn  = (const float*)d_in[3];
    const float* bn  = (const float*)d_in[4];
    const float* Wg  = (const float*)d_in[5];
    const float* bgl = (const float*)d_in[6];
    const float* gb  = (const float*)d_in[7];
    const float* Wc1 = (const float*)d_in[8];
    const float* bc1 = (const float*)d_in[9];
    const float* Wc2 = (const float*)d_in[10];
    const float* bc2 = (const float*)d_in[11];
    const float* Wc3 = (const float*)d_in[12];
    const float* bc3 = (const float*)d_in[13];
    const float* Wa1 = (const float*)d_in[14];
    const float* ba1 = (const float*)d_in[15];
    const float* Wa2 = (const float*)d_in[16];
    const float* ba2 = (const float*)d_in[17];

    const int dyn1 = 128 * 129 * 4;   // 66048 B (k1)
    const int dyn2 = 128 * PITCH * 4; // 67584 B (k2)
    cudaFuncSetAttribute(k1_prep, cudaFuncAttributeMaxDynamicSharedMemorySize, dyn1);
    cudaFuncSetAttribute(k2_gcn, cudaFuncAttributeMaxDynamicSharedMemorySize, dyn2);

    k1_prep<<<dim3(32, 3), 512, dyn1>>>(inp, We, be);
    k2_gcn<<<dim3(32, 10), 512, dyn2>>>(inp, Wn, bn, Wg, bgl, gb);
    k3_reduce<<<256, 256>>>();
    k4_gemm<<<dim3(16, KSPLIT, 2), 128>>>(Wc1, Wa1);
    k5a_act<<<dim3(64, 2), 256>>>(bc1, ba1);
    k5b_heads<<<dim3(32, 2), 256>>>(Wc2, bc2, Wc3, bc3, Wa2, ba2, (float*)d_out);
}

// round 14
// speedup vs baseline: 1.0870x; 1.0004x over previous
#include <cuda_runtime.h>
#include <cstdint>
#include <cstddef>

// ---------------- problem dims ----------------
// B=32, T=10, NOV=3, N=128, F=16, NF=5, EF=2, C=4, SL=2, HID=2048
#define LEAKY(x) ((x) > 0.0f ? (x) : 0.01f * (x))

constexpr int Bc = 32;
constexpr int Nc = 128;
constexpr int HIDc = 2048;
constexpr int ROWc = 389;      // 3N+NF
constexpr int FLATc = 8192;    // C*N*F
constexpr int KSPLIT = 32;     // k4 K-split factor (256 k per CTA)
constexpr int PITCH = 132;     // k2 s_a pitch (16B-aligned rows, conflict-free)

// ---------------- scratch (__device__ globals; no allocs) ----------------
__device__ float g_a1[Bc * Nc * Nc];
__device__ float g_a2[Bc * Nc * Nc];
__device__ float g_rs1[Bc * Nc];
__device__ float g_rs2[Bc * Nc];
__device__ float g_eep[2 * Bc * Nc * 16];   // edge-enc halves
__device__ float g_x2[(size_t)Bc * 10 * 4 * Nc * 16];
__device__ float2 g_flatd[(size_t)Bc * FLATc];   // duplicated pairs (v,v), 2 MB
__device__ float g_part2[(size_t)2 * KSPLIT * Bc * HIDc];
__device__ float g_hh[2 * Bc * HIDc];

// ---------------- helpers ----------------
__device__ __forceinline__ unsigned long long f2pk(float x, float y) {
    unsigned long long d;
    asm("mov.b64 %0, {%1, %2};" : "=l"(d) : "f"(x), "f"(y));
    return d;
}
__device__ __forceinline__ void f2un(float& x, float& y, unsigned long long v) {
    asm("mov.b64 {%0, %1}, %2;" : "=f"(x), "=f"(y) : "l"(v));
}
__device__ __forceinline__ unsigned long long fma2(unsigned long long a,
                                                   unsigned long long b,
                                                   unsigned long long c) {
    unsigned long long d;
    asm("fma.rn.f32x2 %0, %1, %2, %3;" : "=l"(d) : "l"(a), "l"(b), "l"(c));
    return d;
}
__device__ __forceinline__ void cp16(uint32_t smem_dst, const void* gsrc) {
    asm volatile("cp.async.cg.shared.global [%0], [%1], 16;\n" ::
                 "r"(smem_dst), "l"(gsrc));
}
__device__ __forceinline__ void cp4(uint32_t smem_dst, const void* gsrc) {
    asm volatile("cp.async.ca.shared.global [%0], [%1], 4;\n" ::
                 "r"(smem_dst), "l"(gsrc));
}
__device__ __forceinline__ void cp_commit() {
    asm volatile("cp.async.commit_group;\n");
}
__device__ __forceinline__ void cp_wait0() {
    asm volatile("cp.async.wait_group 0;\n" ::: "memory");
}

// ============================================================
// K1: grid (32, 3), block 512, dyn smem 128*129*4
//  y==0: adjacency normalization chain (a1, rs1, a2, rs2)
//  y==1/2: edge-encoder i-half -> g_eep[half]
// ============================================================
__global__ void __launch_bounds__(512)
k1_prep(const float* __restrict__ inp,
        const float* __restrict__ We,
        const float* __restrict__ be) {
    extern __shared__ float s_a[];       // [128][129] (y>0 uses 64 rows)
    __shared__ float s_d[128];
    __shared__ float s_we[32];
    __shared__ float s_be[16];
    __shared__ float s_part[3 * 2048];
    const int b = blockIdx.x, role = blockIdx.y, tid = threadIdx.x;
    const size_t base = (size_t)b * 30 * 128 * ROWc;

    if (role != 0) {
        // ---- edge encoder for i in [h*64, h*64+64) ----
        const int h = role - 1;
        if (tid < 32) s_we[tid] = We[tid];
        if (tid >= 32 && tid < 48) s_be[tid - 32] = be[tid - 32];
        for (int idx = tid; idx < 64 * 128; idx += 512) {
            int i = idx >> 7, j = idx & 127;
            s_a[i * 129 + j] = inp[base + (size_t)(h * 64 + i) * ROWc + j];
        }
        __syncthreads();
        const int j = tid & 127;
        const int q = tid >> 7;
        float acc[16];
#pragma unroll
        for (int f = 0; f < 16; f++) acc[f] = 0.0f;
#pragma unroll 4
        for (int il = q * 16; il < q * 16 + 16; il++) {
            float a = s_a[il * 129 + j];
            const float* ep =
                inp + base + (size_t)(h * 64 + il) * ROWc + 128 + 2 * j;
            float e0 = ep[0], e1 = ep[1];
#pragma unroll
            for (int f = 0; f < 16; f++) {
                float v = fmaf(e0, s_we[f], fmaf(e1, s_we[16 + f], s_be[f]));
                v = LEAKY(v);
                acc[f] = fmaf(v, a, acc[f]);
            }
        }
        if (q) {
#pragma unroll
            for (int f = 0; f < 16; f++)
                s_part[(q - 1) * 2048 + j * 16 + f] = acc[f];
        }
        __syncthreads();
        if (q == 0) {
#pragma unroll
            for (int f = 0; f < 16; f++)
                g_eep[h * 65536 + (b * 128 + j) * 16 + f] =
                    acc[f] + s_part[j * 16 + f] + s_part[2048 + j * 16 + f] +
                    s_part[4096 + j * 16 + f];
        }
        return;
    }

    // ---- role 0: adjacency chain ----
    for (int idx = tid; idx < 128 * 128; idx += 512) {
        int i = idx >> 7, j = idx & 127;
        s_a[i * 129 + j] = inp[base + (size_t)i * ROWc + j];
    }
    __syncthreads();
    {
        const int i = tid & 127, q = tid >> 7;
        float p = 0.0f;
        for (int j = q * 32; j < q * 32 + 32; j++)
            p += (j == i) ? 1.0f : s_a[i * 129 + j];
        s_part[q * 128 + i] = p;
        __syncthreads();
        if (tid < 128) {
            float s = s_part[tid] + s_part[128 + tid] + s_part[256 + tid] +
                      s_part[384 + tid];
            s_d[tid] = 1.0f / sqrtf(fmaxf(s, 1.0f));
        }
        __syncthreads();
    }
    for (int idx = tid; idx < 128 * 128; idx += 512) {
        int i = idx >> 7, j = idx & 127;
        float a0 = (i == j) ? 1.0f : s_a[i * 129 + j];
        float v = s_d[i] * a0 * s_d[j];
        s_a[i * 129 + j] = v;
        g_a1[b * 16384 + idx] = v;
    }
    __syncthreads();
    {
        const int i = tid & 127, q = tid >> 7;
        float p = 0.0f;
        for (int j = q * 32; j < q * 32 + 32; j++) p += s_a[i * 129 + j];
        s_part[q * 128 + i] = p;
        __syncthreads();
        if (tid < 128) {
            float s = s_part[tid] + s_part[128 + tid] + s_part[256 + tid] +
                      s_part[384 + tid];
            g_rs1[b * 128 + tid] = s;
            s_d[tid] = 1.0f / sqrtf(fmaxf(s, 1.0f));
        }
        __syncthreads();
    }
    for (int idx = tid; idx < 128 * 128; idx += 512) {
        int i = idx >> 7, j = idx & 127;
        float v = s_d[i] * s_a[i * 129 + j] * s_d[j];
        s_a[i * 129 + j] = v;
        g_a2[b * 16384 + idx] = v;
    }
    __syncthreads();
    {
        const int i = tid & 127, q = tid >> 7;
        float p = 0.0f;
        for (int j = q * 32; j < q * 32 + 32; j++) p += s_a[i * 129 + j];
        s_part[q * 128 + i] = p;
        __syncthreads();
        if (tid < 128)
            g_rs2[b * 128 + tid] = s_part[tid] + s_part[128 + tid] +
                                   s_part[256 + tid] + s_part[384 + tid];
    }
}

// ============================================================
// K2: per-(b,t) GCN, 512 threads, f32x2 packed math,
// a1/a2 loads overlapped via cp.async; s_a pitch 132 for
// vectorized (LDS.128) a-row reads in the z matmuls.
// grid (32,10), block 512, dynamic smem = 128*132*4
// ============================================================
__global__ void __launch_bounds__(512)
k2_gcn(const float* __restrict__ inp,
       const float* __restrict__ Wn,
       const float* __restrict__ bn,
       const float* __restrict__ Wg,
       const float* __restrict__ bgl,
       const float* __restrict__ gb) {
    extern __shared__ float s_a[];       // [128][PITCH=132]
    __shared__ float s_xs[2048];
    __shared__ float s_z[2048];
    __shared__ float s_wgT[2048];        // [l][c][o][f]
    __shared__ float s_bgl[128];
    __shared__ float s_gb[64];
    __shared__ float s_wn[80];
    __shared__ float s_bn[16];
    __shared__ float s_rs[256];

    const int b = blockIdx.x, t = blockIdx.y, tid = threadIdx.x;
    const uint32_t sa_base = (uint32_t)__cvta_generic_to_shared(s_a);

    for (int idx = tid; idx < 16384; idx += 512) {
        int i = idx >> 7, j = idx & 127;
        cp4(sa_base + (uint32_t)(i * PITCH + j) * 4, &g_a1[b * 16384 + idx]);
    }
    cp_commit();

    for (int i = tid; i < 2048; i += 512) {
        int o = i & 15, f = (i >> 4) & 15, lc = i >> 8;
        s_wgT[(lc * 16 + o) * 16 + f] = Wg[i];
    }
    if (tid < 128) s_bgl[tid] = bgl[tid];
    if (tid < 64) s_gb[tid] = gb[tid];
    if (tid < 80) s_wn[tid] = Wn[tid];
    if (tid < 16) s_bn[tid] = bn[tid];
    if (tid < 128) s_rs[tid] = g_rs1[b * 128 + tid];
    if (tid >= 128 && tid < 256) s_rs[tid] = g_rs2[b * 128 + tid - 128];
    __syncthreads();

    const int n = tid & 127;
    const int f0 = (tid >> 7) * 4;

    // xs = edge_enc(sum of halves) + sum_v leaky(node@Wn + bn)
    {
        float acc[4];
        const float* e0 = &g_eep[(b * 128 + n) * 16 + f0];
        const float* e1 = &g_eep[65536 + (b * 128 + n) * 16 + f0];
#pragma unroll
        for (int f = 0; f < 4; f++) acc[f] = e0[f] + e1[f];
#pragma unroll
        for (int v = 0; v < 3; v++) {
            const float* np =
                inp + ((size_t)(b * 30 + t * 3 + v) * 128 + n) * ROWc + 384;
            float nk0 = np[0], nk1 = np[1], nk2 = np[2], nk3 = np[3], nk4 = np[4];
#pragma unroll
            for (int f = 0; f < 4; f++) {
                int fc = f0 + f;
                float s = s_bn[fc];
                s = fmaf(nk0, s_wn[fc], s);
                s = fmaf(nk1, s_wn[16 + fc], s);
                s = fmaf(nk2, s_wn[32 + fc], s);
                s = fmaf(nk3, s_wn[48 + fc], s);
                s = fmaf(nk4, s_wn[64 + fc], s);
                acc[f] += LEAKY(s);
            }
        }
        *(float4*)&s_xs[n * 16 + f0] = make_float4(acc[0], acc[1], acc[2], acc[3]);
    }
    cp_wait0();
    __syncthreads();

    // z1 = a1 @ xs  (vectorized a-row loads)
    {
        unsigned long long za0 = 0ULL, za1 = 0ULL;
        const float* arow = &s_a[n * PITCH];
#pragma unroll 4
        for (int m4 = 0; m4 < 32; m4++) {
            float4 a4 = *(const float4*)&arow[m4 * 4];
#pragma unroll
            for (int j = 0; j < 4; j++) {
                float a = (j == 0) ? a4.x : (j == 1) ? a4.y : (j == 2) ? a4.z : a4.w;
                unsigned long long ap = f2pk(a, a);
                ulonglong2 x = *(const ulonglong2*)&s_xs[(m4 * 4 + j) * 16 + f0];
                za0 = fma2(ap, x.x, za0);
                za1 = fma2(ap, x.y, za1);
            }
        }
        ulonglong2 zo; zo.x = za0; zo.y = za1;
        *(ulonglong2*)&s_z[n * 16 + f0] = zo;
    }
    __syncthreads();

    // a2 copy overlaps layer-1 mix
    for (int idx = tid; idx < 16384; idx += 512) {
        int i = idx >> 7, j = idx & 127;
        cp4(sa_base + (uint32_t)(i * PITCH + j) * 4, &g_a2[b * 16384 + idx]);
    }
    cp_commit();

    // layer-1 channel mix
    {
        unsigned long long zp[8];
        ulonglong2 q0 = *(const ulonglong2*)&s_z[n * 16];
        ulonglong2 q1 = *(const ulonglong2*)&s_z[n * 16 + 4];
        ulonglong2 q2 = *(const ulonglong2*)&s_z[n * 16 + 8];
        ulonglong2 q3 = *(const ulonglong2*)&s_z[n * 16 + 12];
        zp[0] = q0.x; zp[1] = q0.y; zp[2] = q1.x; zp[3] = q1.y;
        zp[4] = q2.x; zp[5] = q2.y; zp[6] = q3.x; zp[7] = q3.y;
        float rs4 = 4.0f * s_rs[n];
        float outv[4];
#pragma unroll
        for (int o = 0; o < 4; o++) {
            int oc = f0 + o;
            float sum = 0.0f;
#pragma unroll
            for (int c = 0; c < 4; c++) {
                const unsigned long long* wp =
                    (const unsigned long long*)&s_wgT[(c * 16 + oc) * 16];
                unsigned long long a2v = 0ULL;
#pragma unroll
                for (int i = 0; i < 8; i++) a2v = fma2(zp[i], wp[i], a2v);
                float ux, uy; f2un(ux, uy, a2v);
                float u = ux + uy + fmaf(rs4, s_bgl[c * 16 + oc], s_gb[c * 16 + oc]);
                sum += LEAKY(u);
            }
            outv[o] = sum;
        }
        *(float4*)&s_xs[n * 16 + f0] =
            make_float4(outv[0], outv[1], outv[2], outv[3]);
    }
    cp_wait0();
    __syncthreads();

    // z2 = a2 @ xs2  (vectorized a-row loads)
    {
        unsigned long long za0 = 0ULL, za1 = 0ULL;
        const float* arow = &s_a[n * PITCH];
#pragma unroll 4
        for (int m4 = 0; m4 < 32; m4++) {
            float4 a4 = *(const float4*)&arow[m4 * 4];
#pragma unroll
            for (int j = 0; j < 4; j++) {
                float a = (j == 0) ? a4.x : (j == 1) ? a4.y : (j == 2) ? a4.z : a4.w;
                unsigned long long ap = f2pk(a, a);
                ulonglong2 x = *(const ulonglong2*)&s_xs[(m4 * 4 + j) * 16 + f0];
                za0 = fma2(ap, x.x, za0);
                za1 = fma2(ap, x.y, za1);
            }
        }
        ulonglong2 zo; zo.x = za0; zo.y = za1;
        *(ulonglong2*)&s_z[n * 16 + f0] = zo;
    }
    __syncthreads();

    // layer-2 channel mix -> g_x2 (float4 stores)
    {
        unsigned long long zp[8];
        ulonglong2 q0 = *(const ulonglong2*)&s_z[n * 16];
        ulonglong2 q1 = *(const ulonglong2*)&s_z[n * 16 + 4];
        ulonglong2 q2 = *(const ulonglong2*)&s_z[n * 16 + 8];
        ulonglong2 q3 = *(const ulonglong2*)&s_z[n * 16 + 12];
        zp[0] = q0.x; zp[1] = q0.y; zp[2] = q1.x; zp[3] = q1.y;
        zp[4] = q2.x; zp[5] = q2.y; zp[6] = q3.x; zp[7] = q3.y;
        float rs4 = 4.0f * s_rs[128 + n];
        size_t obase = ((size_t)(b * 10 + t) * 4) * 2048 + n * 16 + f0;
#pragma unroll
        for (int c = 0; c < 4; c++) {
            float ov[4];
#pragma unroll
            for (int o = 0; o < 4; o++) {
                int oc = f0 + o;
                const unsigned long long* wp =
                    (const unsigned long long*)&s_wgT[((4 + c) * 16 + oc) * 16];
                unsigned long long a2v = 0ULL;
#pragma unroll
                for (int i = 0; i < 8; i++) a2v = fma2(zp[i], wp[i], a2v);
                float ux, uy; f2un(ux, uy, a2v);
                float u = ux + uy +
                          fmaf(rs4, s_bgl[64 + c * 16 + oc], s_gb[c * 16 + oc]);
                ov[o] = LEAKY(u);
            }
            *(float4*)&g_x2[obase + c * 2048] =
                make_float4(ov[0], ov[1], ov[2], ov[3]);
        }
    }
}

// ============================================================
// K3: reduce over t -> duplicated flat pairs g_flatd.
// grid 256, block 256
// ============================================================
__global__ void k3_reduce() {
    int idx4 = blockIdx.x * 256 + threadIdx.x;   // 0..65535
    int b = idx4 >> 11;
    int j4 = idx4 & 2047;
    const float4* p = (const float4*)&g_x2[(size_t)b * 10 * 8192] + j4;
    float4 s = make_float4(0.f, 0.f, 0.f, 0.f);
#pragma unroll
    for (int t = 0; t < 10; t++) {
        float4 v = p[t * 2048];
        s.x += v.x; s.y += v.y; s.z += v.z; s.w += v.w;
    }
    float2* fd = &g_flatd[(size_t)b * 8192 + j4 * 4];
    fd[0] = make_float2(s.x, s.x);
    fd[1] = make_float2(s.y, s.y);
    fd[2] = make_float2(s.z, s.z);
    fd[3] = make_float2(s.w, s.w);
}

// ============================================================
// K4 v8: flat(32x8192) @ W(8192x2048) x2 heads.
// Both W tile AND pre-duplicated flatd tile staged via double-buffered
// cp.async. Inner loop: pure LDS.128 broadcast + fma2 — no shfl/pack/STS.
// grid (16, 32, 2) = 1024 CTAs, block 128, 6 CTAs/SM.
// ============================================================
__global__ void __launch_bounds__(128, 6)
k4_gemm(const float* __restrict__ Wc1, const float* __restrict__ Wa1) {
    __shared__ float s_w[2][16][128];      // 16 KB  [buf][k][col]
    __shared__ float2 s_fd[2][32][16];     // 8 KB   [buf][row][k] dup pairs
    const int tid = threadIdx.x;
    const int head = blockIdx.z;
    const float* __restrict__ W = head ? Wa1 : Wc1;
    const int colbase = blockIdx.x * 128;
    const int warp = tid >> 5, lane = tid & 31;
    const int rowbase = warp * 8;
    const int kbase = blockIdx.y * 256;

    const uint32_t sw0 = (uint32_t)__cvta_generic_to_shared(&s_w[0][0][0]);
    const uint32_t sw1 = (uint32_t)__cvta_generic_to_shared(&s_w[1][0][0]);
    const uint32_t sf0 = (uint32_t)__cvta_generic_to_shared(&s_fd[0][0][0]);
    const uint32_t sf1 = (uint32_t)__cvta_generic_to_shared(&s_fd[1][0][0]);

    // cp.async index precompute
    const int wkr = tid >> 5, wcq = tid & 31;      // W: 4 chunks strided by 4 k
    const int fdr = tid >> 3, fdc = tid & 7;       // fd: row 0..15 (+16), chunk 0..7

    unsigned long long acc[8][2];
#pragma unroll
    for (int r = 0; r < 8; r++) { acc[r][0] = 0ULL; acc[r][1] = 0ULL; }

    // prologue: stage-0 fills
    {
#pragma unroll
        for (int i = 0; i < 4; i++) {
            int kr = wkr + i * 4;
            cp16(sw0 + (uint32_t)(kr * 128 + wcq * 4) * 4,
                 &W[(size_t)(kbase + kr) * 2048 + colbase + wcq * 4]);
        }
#pragma unroll
        for (int i = 0; i < 2; i++) {
            int row = fdr + i * 16;
            cp16(sf0 + (uint32_t)(row * 16 + fdc * 2) * 8,
                 &g_flatd[(size_t)row * 8192 + kbase + fdc * 2]);
        }
        cp_commit();
    }

    for (int s = 0; s < 16; s++) {
        const int b = s & 1;
        cp_wait0();
        __syncthreads();
        if (s < 15) {
            const uint32_t swn = b ? sw0 : sw1;
            const uint32_t sfn = b ? sf0 : sf1;
            const int kn = kbase + (s + 1) * 16;
#pragma unroll
            for (int i = 0; i < 4; i++) {
                int kr = wkr + i * 4;
                cp16(swn + (uint32_t)(kr * 128 + wcq * 4) * 4,
                     &W[(size_t)(kn + kr) * 2048 + colbase + wcq * 4]);
            }
#pragma unroll
            for (int i = 0; i < 2; i++) {
                int row = fdr + i * 16;
                cp16(sfn + (uint32_t)(row * 16 + fdc * 2) * 8,
                     &g_flatd[(size_t)row * 8192 + kn + fdc * 2]);
            }
            cp_commit();
        }
#pragma unroll
        for (int kp = 0; kp < 8; kp++) {
            ulonglong2 w0 = *(const ulonglong2*)&s_w[b][kp * 2][lane * 4];
            ulonglong2 w1 = *(const ulonglong2*)&s_w[b][kp * 2 + 1][lane * 4];
#pragma unroll
            for (int r = 0; r < 8; r++) {
                // 16B broadcast: (dk, dk1) duplicated pairs
                ulonglong2 d =
                    *(const ulonglong2*)&s_fd[b][rowbase + r][kp * 2];
                acc[r][0] = fma2(d.x, w0.x, acc[r][0]);
                acc[r][1] = fma2(d.x, w0.y, acc[r][1]);
                acc[r][0] = fma2(d.y, w1.x, acc[r][0]);
                acc[r][1] = fma2(d.y, w1.y, acc[r][1]);
            }
        }
    }

    const size_t base = ((size_t)(head * KSPLIT + blockIdx.y)) * 65536;
    const int gcol = colbase + lane * 4;
#pragma unroll
    for (int r = 0; r < 8; r++) {
        float4 o;
        f2un(o.x, o.y, acc[r][0]);
        f2un(o.z, o.w, acc[r][1]);
        *(float4*)&g_part2[base + (size_t)(rowbase + r) * 2048 + gcol] = o;
    }
}

// ============================================================
// K5a: reduce K-split partials + bias + leaky (float4)
// grid (64, 2), block 256
// ============================================================
__global__ void k5a_act(const float* __restrict__ bc1,
                        const float* __restrict__ ba1) {
    const int head = blockIdx.y;
    const int i4 = blockIdx.x * 256 + threadIdx.x;   // 0..16383
    const int col4 = i4 & 511;
    float4 s = ((const float4*)(head ? ba1 : bc1))[col4];
    const float4* p = (const float4*)&g_part2[(size_t)head * KSPLIT * 65536];
#pragma unroll
    for (int pi = 0; pi < KSPLIT; pi++) {
        float4 v = p[(size_t)pi * 16384 + i4];
        s.x += v.x; s.y += v.y; s.z += v.z; s.w += v.w;
    }
    s.x = LEAKY(s.x); s.y = LEAKY(s.y); s.z = LEAKY(s.z); s.w = LEAKY(s.w);
    ((float4*)g_hh)[head * 16384 + i4] = s;
}

// ============================================================
// K5b: small heads, per-head CTAs + W2 prefetch.
// grid (32, 2), block 256
// ============================================================
__global__ void k5b_heads(const float* __restrict__ Wc2,
                          const float* __restrict__ bc2,
                          const float* __restrict__ Wc3,
                          const float* __restrict__ bc3,
                          const float* __restrict__ Wa2,
                          const float* __restrict__ ba2,
                          float* __restrict__ out) {
    __shared__ float s_h[2048];
    __shared__ float s_w[256 * 17];
    __shared__ float s_r[16];
    const int b = blockIdx.x, head = blockIdx.y, tid = threadIdx.x;
    const float* __restrict__ W2 = head ? Wa2 : Wc2;
    const float* __restrict__ b2 = head ? ba2 : bc2;

    {
        const float4* hs = (const float4*)&g_hh[head * 65536 + b * 2048];
        ((float4*)s_h)[tid] = hs[tid];
        ((float4*)s_h)[tid + 256] = hs[tid + 256];
    }
    const int w = tid >> 5, lane = tid & 31;
    float ps[2] = {0.0f, 0.0f};

    float rv[16];
#pragma unroll
    for (int i = 0; i < 16; i++) rv[i] = W2[tid + i * 256];

    for (int c = 0; c < 8; c++) {
        __syncthreads();
#pragma unroll
        for (int i = 0; i < 16; i++) {
            int idx = tid + i * 256;
            s_w[(idx >> 4) * 17 + (idx & 15)] = rv[i];
        }
        __syncthreads();
        if (c < 7) {
#pragma unroll
            for (int i = 0; i < 16; i++)
                rv[i] = W2[(c + 1) * 4096 + tid + i * 256];
        }
#pragma unroll
        for (int dd = 0; dd < 2; dd++) {
            const int f = w + dd * 8;
            float s = 0.0f;
#pragma unroll
            for (int ki = 0; ki < 8; ki++) {
                int k = ki * 32 + lane;
                s = fmaf(s_h[c * 256 + k], s_w[k * 17 + f], s);
            }
            ps[dd] += s;
        }
    }
#pragma unroll
    for (int dd = 0; dd < 2; dd++) {
        float s = ps[dd];
#pragma unroll
        for (int off = 16; off; off >>= 1) s += __shfl_down_sync(0xffffffffu, s, off);
        if (lane == 0) {
            int f = w + dd * 8;
            float v = s + b2[f];
            s_r[f] = LEAKY(v);
        }
    }
    __syncthreads();
    if (head == 0) {
        if (tid == 0) {
            float cr = bc3[0];
#pragma unroll
            for (int f = 0; f < 16; f++) cr = fmaf(s_r[f], Wc3[f], cr);
            out[b] = cr;
        }
    } else {
        if (tid < 16) out[32 + b * 16 + tid] = s_r[tid];
    }
}

// ============================================================
extern "C" void kernel_launch(void* const* d_in, const int* in_sizes, int n_in,
                              void* d_out, int out_size) {
    (void)in_sizes; (void)n_in; (void)out_size;
    const float* inp = (const float*)d_in[0];
    const float* We  = (const float*)d_in[1];
    const float* be  = (const float*)d_in[2];
    const float* Wn  = (const float*)d_in[3];
    const float* bn  = (const float*)d_in[4];
    const float* Wg  = (const float*)d_in[5];
    const float* bgl = (const float*)d_in[6];
    const float* gb  = (const float*)d_in[7];
    const float* Wc1 = (const float*)d_in[8];
    const float* bc1 = (const float*)d_in[9];
    const float* Wc2 = (const float*)d_in[10];
    const float* bc2 = (const float*)d_in[11];
    const float* Wc3 = (const float*)d_in[12];
    const float* bc3 = (const float*)d_in[13];
    const float* Wa1 = (const float*)d_in[14];
    const float* ba1 = (const float*)d_in[15];
    const float* Wa2 = (const float*)d_in[16];
    const float* ba2 = (const float*)d_in[17];

    const int dyn1 = 128 * 129 * 4;   // 66048 B (k1)
    const int dyn2 = 128 * PITCH * 4; // 67584 B (k2)
    cudaFuncSetAttribute(k1_prep, cudaFuncAttributeMaxDynamicSharedMemorySize, dyn1);
    cudaFuncSetAttribute(k2_gcn, cudaFuncAttributeMaxDynamicSharedMemorySize, dyn2);

    k1_prep<<<dim3(32, 3), 512, dyn1>>>(inp, We, be);
    k2_gcn<<<dim3(32, 10), 512, dyn2>>>(inp, Wn, bn, Wg, bgl, gb);
    k3_reduce<<<256, 256>>>();
    k4_gemm<<<dim3(16, KSPLIT, 2), 128>>>(Wc1, Wa1);
    k5a_act<<<dim3(64, 2), 256>>>(bc1, ba1);
    k5b_heads<<<dim3(32, 2), 256>>>(Wc2, bc2, Wc3, bc3, Wa2, ba2, (float*)d_out);
}